// round 2
// baseline (speedup 1.0000x reference)
#include <cuda_runtime.h>

#define B_   4
#define S_   2048
#define D_   512
#define H_   8
#define DK_  64

// Scratch (allocation-free: __device__ globals)
__device__ float g_Qh[B_*H_*S_*DK_];
__device__ float g_Kh[B_*H_*S_*DK_];
__device__ float g_Vh[B_*H_*S_*DK_];
__device__ float g_Oc[B_*S_*D_];     // attention output, head-concat layout [B*S, 512]

__device__ __forceinline__ float comp4(const float4& v, int t) {
    return t == 0 ? v.x : t == 1 ? v.y : t == 2 ? v.z : v.w;
}

// ---------------------------------------------------------------------------
// Projection: Y[b,h,s,k] = sum_d X[b,s,d] * W[h,d,k]
// grid = (H, (B*S)/64), block = 256. Each block: 64 rows x one head (64 cols).
// ---------------------------------------------------------------------------
__global__ __launch_bounds__(256) void proj_kernel(const float* __restrict__ X,
                                                   const float* __restrict__ W,
                                                   int which)
{
    float* __restrict__ Y = (which == 0) ? g_Qh : (which == 1) ? g_Kh : g_Vh;

    __shared__ float As[64][36];   // A tile [m][k], pad 36 -> float4-aligned rows
    __shared__ float Bs[32][68];   // B tile [k][n], pad 68 -> float4-aligned rows

    const int h  = blockIdx.x;
    const int m0 = blockIdx.y * 64;
    const int tid = threadIdx.x;
    const int tx = tid & 15, ty = tid >> 4;

    const float* __restrict__ Wh = W + (size_t)h * (D_ * DK_);

    float acc[4][4] = {};

    for (int k0 = 0; k0 < D_; k0 += 32) {
        // load A 64x32 (float4 both sides)
        {
            int f = tid;
            #pragma unroll
            for (int it = 0; it < 2; it++, f += 256) {
                int r = f >> 3, c4 = (f & 7) << 2;
                *(float4*)&As[r][c4] =
                    *(const float4*)(X + (size_t)(m0 + r) * D_ + k0 + c4);
            }
        }
        // load B 32x64 from W[h][d][k] (float4 both sides)
        {
            int f = tid;
            #pragma unroll
            for (int it = 0; it < 2; it++, f += 256) {
                int c = f >> 4, k4 = (f & 15) << 2;
                *(float4*)&Bs[c][k4] = *(const float4*)(Wh + (size_t)(k0 + c) * DK_ + k4);
            }
        }
        __syncthreads();

        #pragma unroll
        for (int kk = 0; kk < 32; kk += 4) {
            float4 a[4];
            #pragma unroll
            for (int i = 0; i < 4; i++)
                a[i] = *(const float4*)&As[ty * 4 + i][kk];
            #pragma unroll
            for (int t = 0; t < 4; t++) {
                float4 b4 = *(const float4*)&Bs[kk + t][tx * 4];
                #pragma unroll
                for (int i = 0; i < 4; i++) {
                    float av = comp4(a[i], t);
                    acc[i][0] += av * b4.x;
                    acc[i][1] += av * b4.y;
                    acc[i][2] += av * b4.z;
                    acc[i][3] += av * b4.w;
                }
            }
        }
        __syncthreads();
    }

    #pragma unroll
    for (int i = 0; i < 4; i++) {
        int m = m0 + ty * 4 + i;
        int b = m / S_, s = m % S_;
        float4 v = make_float4(acc[i][0], acc[i][1], acc[i][2], acc[i][3]);
        *(float4*)(Y + ((size_t)((b * H_ + h) * S_ + s)) * DK_ + tx * 4) = v;
    }
}

// ---------------------------------------------------------------------------
// Flash attention per (b, h, q-block of 64). Online softmax, dk = 64.
// Dynamic smem: Qs | Kt (transposed) | Vs | Ps, each 64x68 floats.
// ---------------------------------------------------------------------------
__global__ __launch_bounds__(256) void attn_kernel()
{
    extern __shared__ float sm[];
    float (*Qs)[68] = (float(*)[68])(sm);
    float (*Kt)[68] = (float(*)[68])(sm + 1 * 64 * 68);  // Kt[k][s]
    float (*Vs)[68] = (float(*)[68])(sm + 2 * 64 * 68);  // Vs[s][k]
    float (*Ps)[68] = (float(*)[68])(sm + 3 * 64 * 68);  // Ps[q][s]

    const int q0 = blockIdx.x * 64;
    const int h  = blockIdx.y;
    const int b  = blockIdx.z;

    const float* __restrict__ Qb = g_Qh + ((size_t)(b * H_ + h) * S_) * DK_;
    const float* __restrict__ Kb = g_Kh + ((size_t)(b * H_ + h) * S_) * DK_;
    const float* __restrict__ Vb = g_Vh + ((size_t)(b * H_ + h) * S_) * DK_;

    const int tid = threadIdx.x;
    const int tx = tid & 15, ty = tid >> 4;

    // Load Q tile (64x64)
    {
        int f = tid;
        #pragma unroll
        for (int it = 0; it < 4; it++, f += 256) {
            int r = f >> 4, k4 = (f & 15) << 2;
            *(float4*)&Qs[r][k4] = *(const float4*)(Qb + (size_t)(q0 + r) * DK_ + k4);
        }
    }

    float accO[4][4] = {};
    float mrun[4], lrun[4];
    #pragma unroll
    for (int i = 0; i < 4; i++) { mrun[i] = -1e30f; lrun[i] = 0.f; }

    const float Cc = 0.125f * 1.4426950408889634f;   // (1/sqrt(64)) * log2(e)

    for (int s0 = 0; s0 < S_; s0 += 64) {
        // Load K (transposed into Kt[k][s]) and V (natural)
        {
            int f = tid;
            #pragma unroll
            for (int it = 0; it < 4; it++, f += 256) {
                int r = f >> 4, k4 = (f & 15) << 2;
                float4 kv = *(const float4*)(Kb + (size_t)(s0 + r) * DK_ + k4);
                Kt[k4+0][r] = kv.x; Kt[k4+1][r] = kv.y;
                Kt[k4+2][r] = kv.z; Kt[k4+3][r] = kv.w;
                *(float4*)&Vs[r][k4] = *(const float4*)(Vb + (size_t)(s0 + r) * DK_ + k4);
            }
        }
        __syncthreads();

        // Scores: S[i][j] = sum_k Q[i][k] * K[j][k]  (k unrolled by 4, float4 Q)
        float sacc[4][4] = {};
        #pragma unroll
        for (int k = 0; k < 64; k += 4) {
            float4 qv[4];
            #pragma unroll
            for (int i = 0; i < 4; i++)
                qv[i] = *(const float4*)&Qs[ty * 4 + i][k];
            #pragma unroll
            for (int t = 0; t < 4; t++) {
                float4 k4v = *(const float4*)&Kt[k + t][tx * 4];
                #pragma unroll
                for (int i = 0; i < 4; i++) {
                    float q = comp4(qv[i], t);
                    sacc[i][0] += q * k4v.x;
                    sacc[i][1] += q * k4v.y;
                    sacc[i][2] += q * k4v.z;
                    sacc[i][3] += q * k4v.w;
                }
            }
        }

        // Online softmax (row groups of 16 lanes: tx = lane bits 0..3)
        #pragma unroll
        for (int i = 0; i < 4; i++) {
            float mloc = fmaxf(fmaxf(sacc[i][0], sacc[i][1]),
                               fmaxf(sacc[i][2], sacc[i][3]));
            #pragma unroll
            for (int off = 8; off >= 1; off >>= 1)
                mloc = fmaxf(mloc, __shfl_xor_sync(0xffffffffu, mloc, off));

            float mnew  = fmaxf(mrun[i], mloc);
            float scale = exp2f((mrun[i] - mnew) * Cc);
            float p0 = exp2f((sacc[i][0] - mnew) * Cc);
            float p1 = exp2f((sacc[i][1] - mnew) * Cc);
            float p2 = exp2f((sacc[i][2] - mnew) * Cc);
            float p3 = exp2f((sacc[i][3] - mnew) * Cc);

            float rs = (p0 + p1) + (p2 + p3);
            #pragma unroll
            for (int off = 8; off >= 1; off >>= 1)
                rs += __shfl_xor_sync(0xffffffffu, rs, off);

            lrun[i] = lrun[i] * scale + rs;
            mrun[i] = mnew;
            accO[i][0] *= scale; accO[i][1] *= scale;
            accO[i][2] *= scale; accO[i][3] *= scale;

            *(float4*)&Ps[ty * 4 + i][tx * 4] = make_float4(p0, p1, p2, p3);
        }
        __syncthreads();

        // O += P @ V  (s unrolled by 4, float4 P)
        #pragma unroll
        for (int s = 0; s < 64; s += 4) {
            float4 pv[4];
            #pragma unroll
            for (int i = 0; i < 4; i++)
                pv[i] = *(const float4*)&Ps[ty * 4 + i][s];
            #pragma unroll
            for (int t = 0; t < 4; t++) {
                float4 v4 = *(const float4*)&Vs[s + t][tx * 4];
                #pragma unroll
                for (int i = 0; i < 4; i++) {
                    float p = comp4(pv[i], t);
                    accO[i][0] += p * v4.x;
                    accO[i][1] += p * v4.y;
                    accO[i][2] += p * v4.z;
                    accO[i][3] += p * v4.w;
                }
            }
        }
        __syncthreads();
    }

    // Epilogue: normalize and write head-concat layout [b*S + q, h*64 + k]
    #pragma unroll
    for (int i = 0; i < 4; i++) {
        float inv = 1.f / lrun[i];
        float4 v = make_float4(accO[i][0] * inv, accO[i][1] * inv,
                               accO[i][2] * inv, accO[i][3] * inv);
        *(float4*)(g_Oc + (size_t)(b * S_ + q0 + ty * 4 + i) * D_ + h * DK_ + tx * 4) = v;
    }
}

// ---------------------------------------------------------------------------
// Output projection: out[m, n] = sum_d Oc[m, d] * WO[d, n]  (8192x512x512)
// grid = (512/64, 8192/64), block = 256.
// ---------------------------------------------------------------------------
__global__ __launch_bounds__(256) void gemm_out_kernel(const float* __restrict__ WO,
                                                       float* __restrict__ out)
{
    __shared__ float As[64][36];
    __shared__ float Bs[32][68];

    const int n0 = blockIdx.x * 64;
    const int m0 = blockIdx.y * 64;
    const int tid = threadIdx.x;
    const int tx = tid & 15, ty = tid >> 4;

    float acc[4][4] = {};

    for (int k0 = 0; k0 < D_; k0 += 32) {
        {
            int f = tid;
            #pragma unroll
            for (int it = 0; it < 2; it++, f += 256) {
                int r = f >> 3, c4 = (f & 7) << 2;
                *(float4*)&As[r][c4] =
                    *(const float4*)(g_Oc + (size_t)(m0 + r) * D_ + k0 + c4);
            }
        }
        {
            int f = tid;
            #pragma unroll
            for (int it = 0; it < 2; it++, f += 256) {
                int c = f >> 4, k4 = (f & 15) << 2;
                *(float4*)&Bs[c][k4] = *(const float4*)(WO + (size_t)(k0 + c) * D_ + n0 + k4);
            }
        }
        __syncthreads();

        #pragma unroll
        for (int kk = 0; kk < 32; kk += 4) {
            float4 a[4];
            #pragma unroll
            for (int i = 0; i < 4; i++)
                a[i] = *(const float4*)&As[ty * 4 + i][kk];
            #pragma unroll
            for (int t = 0; t < 4; t++) {
                float4 b4 = *(const float4*)&Bs[kk + t][tx * 4];
                #pragma unroll
                for (int i = 0; i < 4; i++) {
                    float av = comp4(a[i], t);
                    acc[i][0] += av * b4.x;
                    acc[i][1] += av * b4.y;
                    acc[i][2] += av * b4.z;
                    acc[i][3] += av * b4.w;
                }
            }
        }
        __syncthreads();
    }

    #pragma unroll
    for (int i = 0; i < 4; i++) {
        int m = m0 + ty * 4 + i;
        float4 v = make_float4(acc[i][0], acc[i][1], acc[i][2], acc[i][3]);
        *(float4*)(out + (size_t)m * D_ + n0 + tx * 4) = v;
    }
}

// ---------------------------------------------------------------------------
extern "C" void kernel_launch(void* const* d_in, const int* in_sizes, int n_in,
                              void* d_out, int out_size)
{
    const float* Q  = (const float*)d_in[0];
    const float* K  = (const float*)d_in[1];
    const float* V  = (const float*)d_in[2];
    const float* WQ = (const float*)d_in[3];
    const float* WK = (const float*)d_in[4];
    const float* WV = (const float*)d_in[5];
    const float* WO = (const float*)d_in[6];
    float* out = (float*)d_out;

    dim3 pgrid(H_, (B_ * S_) / 64);
    proj_kernel<<<pgrid, 256>>>(Q, WQ, 0);
    proj_kernel<<<pgrid, 256>>>(K, WK, 1);
    proj_kernel<<<pgrid, 256>>>(V, WV, 2);

    size_t smem = (size_t)4 * 64 * 68 * sizeof(float);   // 69632 B
    cudaFuncSetAttribute(attn_kernel,
                         cudaFuncAttributeMaxDynamicSharedMemorySize, (int)smem);
    attn_kernel<<<dim3(S_ / 64, H_, B_), 256, smem>>>();

    gemm_out_kernel<<<dim3(D_ / 64, (B_ * S_) / 64), 256>>>(WO, out);
}

// round 4
// speedup vs baseline: 1.0201x; 1.0201x over previous
#include <cuda_runtime.h>
#include <cstdint>

#define B_   4
#define S_   2048
#define D_   512
#define H_   8
#define DK_  64
#define QROWS 64
#define STILE 64

// Scratch (allocation-free: __device__ globals)
__device__ float g_Qh[B_*H_*S_*DK_];
__device__ float g_Kh[B_*H_*S_*DK_];
__device__ float g_Vh[B_*H_*S_*DK_];
__device__ float g_Oc[B_*S_*D_];     // attention output, head-concat layout [B*S, 512]

__device__ __forceinline__ float comp4(const float4& v, int t) {
    return t == 0 ? v.x : t == 1 ? v.y : t == 2 ? v.z : v.w;
}

// ===========================================================================
// mma.sync tf32 helpers (baseline PTX, works on compute_103 target)
// ===========================================================================
__device__ __forceinline__ uint32_t f2tf32(float x) {
    uint32_t r; asm("cvt.rna.tf32.f32 %0, %1;" : "=r"(r) : "f"(x)); return r;
}
__device__ __forceinline__ void mma8(float* d,
                                     uint32_t a0, uint32_t a1, uint32_t a2, uint32_t a3,
                                     uint32_t b0, uint32_t b1) {
    asm volatile("mma.sync.aligned.m16n8k8.row.col.f32.tf32.tf32.f32 "
                 "{%0,%1,%2,%3}, {%4,%5,%6,%7}, {%8,%9}, {%0,%1,%2,%3};"
                 : "+f"(d[0]), "+f"(d[1]), "+f"(d[2]), "+f"(d[3])
                 : "r"(a0), "r"(a1), "r"(a2), "r"(a3), "r"(b0), "r"(b1));
}

// Permuted tile layout: element (r, k) of a 64-row x 64-col tile lives at word
//   (kstep*64 + r)*8 + (kin&3)*2 + (kin>>2),  kstep = k>>3, kin = k&7.
// Fragment regs (k = t and t+4 of one kstep) are then one aligned LDS.64.
__device__ __forceinline__ uint32_t pw(int ks, int r, int kin) {
    return (uint32_t)((ks * 64 + r) * 8 + ((kin & 3) * 2 + (kin >> 2)));
}

// smem word offsets (each tile = 8*64*8 = 4096 words = 16KB)
#define W_QHI 0
#define W_QLO 4096
#define W_KHI 8192
#define W_KLO 12288
#define W_VT  16384
#define W_PS  20480
#define SMEM_WORDS 24576   // 96 KB

// ===========================================================================
// Tensor-core flash attention: CTA = (b, h, 64 q-rows), 128 threads / 4 warps.
// QK = Qhi*Khi + Qlo*Khi + Qhi*Klo (split tf32, fp32-grade scores).
// PV = single tf32. O accumulated in registers with online softmax.
// ===========================================================================
__global__ __launch_bounds__(128) void attn_mma_kernel()
{
    extern __shared__ uint32_t smw[];

    const int tid  = threadIdx.x;
    const int lane = tid & 31;
    const int w    = tid >> 5;
    const int g    = lane >> 2;   // group id (row base within m16)
    const int t    = lane & 3;    // thread-in-group

    const int q0 = blockIdx.x * QROWS;
    const int h  = blockIdx.y;
    const int b  = blockIdx.z;
    const float* __restrict__ Qb = g_Qh + ((size_t)(b * H_ + h) * S_) * DK_;
    const float* __restrict__ Kb = g_Kh + ((size_t)(b * H_ + h) * S_) * DK_;
    const float* __restrict__ Vb = g_Vh + ((size_t)(b * H_ + h) * S_) * DK_;

    const int lr = tid >> 1;          // load row 0..63
    const int lc = (tid & 1) * 32;    // load col base

    // --- Load Q tile, split hi/lo, store permuted ---
    {
        const float4* src = (const float4*)(Qb + (size_t)(q0 + lr) * DK_ + lc);
        #pragma unroll
        for (int i = 0; i < 8; i++) {
            float4 v = src[i];
            int c = lc + i * 4, ks = c >> 3;
            #pragma unroll
            for (int d = 0; d < 4; d++) {
                float x = comp4(v, d);
                uint32_t hb = __float_as_uint(x) & 0xFFFFE000u;  // exact hi split
                float lo = x - __uint_as_float(hb);
                int kin = (c & 7) + d;
                smw[W_QHI + pw(ks, lr, kin)] = hb;
                smw[W_QLO + pw(ks, lr, kin)] = f2tf32(lo);
            }
        }
    }

    float o[8][4];
    #pragma unroll
    for (int nt = 0; nt < 8; nt++)
        #pragma unroll
        for (int j = 0; j < 4; j++) o[nt][j] = 0.f;
    float mrun[2] = {-1e30f, -1e30f}, lrun[2] = {0.f, 0.f};
    const float Cc = 0.125f * 1.4426950408889634f;

    const int row0 = w * 16 + g;

    for (int it = 0; it < S_ / STILE; it++) {
        const int s0 = it * STILE;

        // --- Load K tile (split hi/lo) + V tile (transposed, single tf32) ---
        {
            const float4* ksrc = (const float4*)(Kb + (size_t)(s0 + lr) * DK_ + lc);
            const float4* vsrc = (const float4*)(Vb + (size_t)(s0 + lr) * DK_ + lc);
            #pragma unroll
            for (int i = 0; i < 8; i++) {
                float4 kv = ksrc[i];
                float4 vv = vsrc[i];
                int c = lc + i * 4, ks = c >> 3;
                #pragma unroll
                for (int d = 0; d < 4; d++) {
                    float x = comp4(kv, d);
                    uint32_t hb = __float_as_uint(x) & 0xFFFFE000u;
                    float lo = x - __uint_as_float(hb);
                    int kin = (c & 7) + d;
                    smw[W_KHI + pw(ks, lr, kin)] = hb;
                    smw[W_KLO + pw(ks, lr, kin)] = f2tf32(lo);
                    // V transposed: B[k=s][n=dk]  ->  ks = lr>>3, kin = lr&7, r = c+d
                    smw[W_VT + pw(lr >> 3, c + d, lr & 7)] = f2tf32(comp4(vv, d));
                }
            }
        }
        __syncthreads();

        // --- QK: split tf32, 3 MMAs per (ks, nt) ---
        float accS[8][4];
        #pragma unroll
        for (int nt = 0; nt < 8; nt++)
            #pragma unroll
            for (int j = 0; j < 4; j++) accS[nt][j] = 0.f;

        #pragma unroll
        for (int ks = 0; ks < 8; ks++) {
            uint2 qh0 = *(const uint2*)(smw + W_QHI + (ks * 64 + row0) * 8 + t * 2);
            uint2 qh1 = *(const uint2*)(smw + W_QHI + (ks * 64 + row0 + 8) * 8 + t * 2);
            uint2 ql0 = *(const uint2*)(smw + W_QLO + (ks * 64 + row0) * 8 + t * 2);
            uint2 ql1 = *(const uint2*)(smw + W_QLO + (ks * 64 + row0 + 8) * 8 + t * 2);
            #pragma unroll
            for (int nt = 0; nt < 8; nt++) {
                uint32_t boff = (ks * 64 + nt * 8 + g) * 8 + t * 2;
                uint2 bh = *(const uint2*)(smw + W_KHI + boff);
                uint2 bl = *(const uint2*)(smw + W_KLO + boff);
                mma8(accS[nt], qh0.x, qh1.x, qh0.y, qh1.y, bh.x, bh.y);
                mma8(accS[nt], ql0.x, ql1.x, ql0.y, ql1.y, bh.x, bh.y);
                mma8(accS[nt], qh0.x, qh1.x, qh0.y, qh1.y, bl.x, bl.y);
            }
        }

        // --- Online softmax (rows row0, row0+8; quad lanes share a row) ---
        #pragma unroll
        for (int j = 0; j < 2; j++) {
            float m = -1e30f;
            #pragma unroll
            for (int nt = 0; nt < 8; nt++)
                m = fmaxf(m, fmaxf(accS[nt][2 * j], accS[nt][2 * j + 1]));
            m = fmaxf(m, __shfl_xor_sync(0xffffffffu, m, 1));
            m = fmaxf(m, __shfl_xor_sync(0xffffffffu, m, 2));

            float mnew = fmaxf(mrun[j], m);
            float scl  = exp2f((mrun[j] - mnew) * Cc);
            mrun[j] = mnew;

            int prow = row0 + 8 * j;
            float sum = 0.f;
            #pragma unroll
            for (int nt = 0; nt < 8; nt++) {
                float p0 = exp2f((accS[nt][2 * j]     - mnew) * Cc);
                float p1 = exp2f((accS[nt][2 * j + 1] - mnew) * Cc);
                sum += p0 + p1;
                smw[W_PS + pw(nt, prow, t * 2)]     = f2tf32(p0);
                smw[W_PS + pw(nt, prow, t * 2 + 1)] = f2tf32(p1);
                o[nt][2 * j]     *= scl;
                o[nt][2 * j + 1] *= scl;
            }
            sum += __shfl_xor_sync(0xffffffffu, sum, 1);
            sum += __shfl_xor_sync(0xffffffffu, sum, 2);
            lrun[j] = lrun[j] * scl + sum;
        }
        __syncthreads();

        // --- PV: O += P @ V (single tf32) ---
        #pragma unroll
        for (int ks = 0; ks < 8; ks++) {
            uint2 p0 = *(const uint2*)(smw + W_PS + (ks * 64 + row0) * 8 + t * 2);
            uint2 p1 = *(const uint2*)(smw + W_PS + (ks * 64 + row0 + 8) * 8 + t * 2);
            #pragma unroll
            for (int nt = 0; nt < 8; nt++) {
                uint2 bv = *(const uint2*)(smw + W_VT + (ks * 64 + nt * 8 + g) * 8 + t * 2);
                mma8(o[nt], p0.x, p1.x, p0.y, p1.y, bv.x, bv.y);
            }
        }
        __syncthreads();   // protect K/V/P before next tile overwrites
    }

    // --- Epilogue: normalize, write head-concat layout ---
    #pragma unroll
    for (int j = 0; j < 2; j++) {
        float inv = 1.f / lrun[j];
        int r = row0 + 8 * j;
        float* dst = g_Oc + (size_t)(b * S_ + q0 + r) * D_ + h * DK_;
        #pragma unroll
        for (int nt = 0; nt < 8; nt++) {
            float2 v = make_float2(o[nt][2 * j] * inv, o[nt][2 * j + 1] * inv);
            *(float2*)(dst + nt * 8 + t * 2) = v;
        }
    }
}

// ---------------------------------------------------------------------------
// Projection: Y[b,h,s,k] = sum_d X[b,s,d] * W[h,d,k]   (SIMT fp32)
// ---------------------------------------------------------------------------
__global__ __launch_bounds__(256) void proj_kernel(const float* __restrict__ X,
                                                   const float* __restrict__ W,
                                                   int which)
{
    float* __restrict__ Y = (which == 0) ? g_Qh : (which == 1) ? g_Kh : g_Vh;

    __shared__ float As[64][36];
    __shared__ float Bs[32][68];

    const int h  = blockIdx.x;
    const int m0 = blockIdx.y * 64;
    const int tid = threadIdx.x;
    const int tx = tid & 15, ty = tid >> 4;

    const float* __restrict__ Wh = W + (size_t)h * (D_ * DK_);

    float acc[4][4] = {};

    for (int k0 = 0; k0 < D_; k0 += 32) {
        {
            int f = tid;
            #pragma unroll
            for (int it = 0; it < 2; it++, f += 256) {
                int r = f >> 3, c4 = (f & 7) << 2;
                *(float4*)&As[r][c4] = *(const float4*)(X + (size_t)(m0 + r) * D_ + k0 + c4);
            }
        }
        {
            int f = tid;
            #pragma unroll
            for (int it = 0; it < 2; it++, f += 256) {
                int c = f >> 4, k4 = (f & 15) << 2;
                *(float4*)&Bs[c][k4] = *(const float4*)(Wh + (size_t)(k0 + c) * DK_ + k4);
            }
        }
        __syncthreads();

        #pragma unroll
        for (int kk = 0; kk < 32; kk += 4) {
            float4 a[4];
            #pragma unroll
            for (int i = 0; i < 4; i++) a[i] = *(const float4*)&As[ty * 4 + i][kk];
            #pragma unroll
            for (int tq = 0; tq < 4; tq++) {
                float4 b4 = *(const float4*)&Bs[kk + tq][tx * 4];
                #pragma unroll
                for (int i = 0; i < 4; i++) {
                    float av = comp4(a[i], tq);
                    acc[i][0] += av * b4.x;
                    acc[i][1] += av * b4.y;
                    acc[i][2] += av * b4.z;
                    acc[i][3] += av * b4.w;
                }
            }
        }
        __syncthreads();
    }

    #pragma unroll
    for (int i = 0; i < 4; i++) {
        int m = m0 + ty * 4 + i;
        int b = m / S_, s = m % S_;
        float4 v = make_float4(acc[i][0], acc[i][1], acc[i][2], acc[i][3]);
        *(float4*)(Y + ((size_t)((b * H_ + h) * S_ + s)) * DK_ + tx * 4) = v;
    }
}

// ---------------------------------------------------------------------------
// Output projection: out[m, n] = sum_d Oc[m, d] * WO[d, n]  (SIMT fp32)
// ---------------------------------------------------------------------------
__global__ __launch_bounds__(256) void gemm_out_kernel(const float* __restrict__ WO,
                                                       float* __restrict__ out)
{
    __shared__ float As[64][36];
    __shared__ float Bs[32][68];

    const int n0 = blockIdx.x * 64;
    const int m0 = blockIdx.y * 64;
    const int tid = threadIdx.x;
    const int tx = tid & 15, ty = tid >> 4;

    float acc[4][4] = {};

    for (int k0 = 0; k0 < D_; k0 += 32) {
        {
            int f = tid;
            #pragma unroll
            for (int it = 0; it < 2; it++, f += 256) {
                int r = f >> 3, c4 = (f & 7) << 2;
                *(float4*)&As[r][c4] = *(const float4*)(g_Oc + (size_t)(m0 + r) * D_ + k0 + c4);
            }
        }
        {
            int f = tid;
            #pragma unroll
            for (int it = 0; it < 2; it++, f += 256) {
                int c = f >> 4, k4 = (f & 15) << 2;
                *(float4*)&Bs[c][k4] = *(const float4*)(WO + (size_t)(k0 + c) * D_ + n0 + k4);
            }
        }
        __syncthreads();

        #pragma unroll
        for (int kk = 0; kk < 32; kk += 4) {
            float4 a[4];
            #pragma unroll
            for (int i = 0; i < 4; i++) a[i] = *(const float4*)&As[ty * 4 + i][kk];
            #pragma unroll
            for (int tq = 0; tq < 4; tq++) {
                float4 b4 = *(const float4*)&Bs[kk + tq][tx * 4];
                #pragma unroll
                for (int i = 0; i < 4; i++) {
                    float av = comp4(a[i], tq);
                    acc[i][0] += av * b4.x;
                    acc[i][1] += av * b4.y;
                    acc[i][2] += av * b4.z;
                    acc[i][3] += av * b4.w;
                }
            }
        }
        __syncthreads();
    }

    #pragma unroll
    for (int i = 0; i < 4; i++) {
        int m = m0 + ty * 4 + i;
        float4 v = make_float4(acc[i][0], acc[i][1], acc[i][2], acc[i][3]);
        *(float4*)(out + (size_t)m * D_ + n0 + tx * 4) = v;
    }
}

// ---------------------------------------------------------------------------
extern "C" void kernel_launch(void* const* d_in, const int* in_sizes, int n_in,
                              void* d_out, int out_size)
{
    const float* Q  = (const float*)d_in[0];
    const float* K  = (const float*)d_in[1];
    const float* V  = (const float*)d_in[2];
    const float* WQ = (const float*)d_in[3];
    const float* WK = (const float*)d_in[4];
    const float* WV = (const float*)d_in[5];
    const float* WO = (const float*)d_in[6];
    float* out = (float*)d_out;

    dim3 pgrid(H_, (B_ * S_) / 64);
    proj_kernel<<<pgrid, 256>>>(Q, WQ, 0);
    proj_kernel<<<pgrid, 256>>>(K, WK, 1);
    proj_kernel<<<pgrid, 256>>>(V, WV, 2);

    size_t smem = SMEM_WORDS * sizeof(uint32_t);   // 96 KB
    cudaFuncSetAttribute(attn_mma_kernel,
                         cudaFuncAttributeMaxDynamicSharedMemorySize, (int)smem);
    attn_mma_kernel<<<dim3(S_ / QROWS, H_, B_), 128, smem>>>();

    gemm_out_kernel<<<dim3(D_ / 64, (B_ * S_) / 64), 256>>>(WO, out);
}

// round 5
// speedup vs baseline: 1.4137x; 1.3858x over previous
#include <cuda_runtime.h>
#include <cstdint>

#define B_   4
#define S_   2048
#define D_   512
#define H_   8
#define DK_  64
#define QROWS 64
#define STILE 64

// Scratch (allocation-free: __device__ globals)
__device__ float g_Qh[B_*H_*S_*DK_];
__device__ float g_Kh[B_*H_*S_*DK_];
__device__ float g_Vh[B_*H_*S_*DK_];
__device__ float g_Oc[B_*S_*D_];     // attention output, head-concat layout [B*S, 512]

__device__ __forceinline__ float comp4(const float4& v, int t) {
    return t == 0 ? v.x : t == 1 ? v.y : t == 2 ? v.z : v.w;
}

// ===========================================================================
// mma.sync tf32 helpers (baseline PTX, works on compute_103 target)
// ===========================================================================
__device__ __forceinline__ uint32_t f2tf32(float x) {
    uint32_t r; asm("cvt.rna.tf32.f32 %0, %1;" : "=r"(r) : "f"(x)); return r;
}
__device__ __forceinline__ void mma8(float* d,
                                     uint32_t a0, uint32_t a1, uint32_t a2, uint32_t a3,
                                     uint32_t b0, uint32_t b1) {
    asm volatile("mma.sync.aligned.m16n8k8.row.col.f32.tf32.tf32.f32 "
                 "{%0,%1,%2,%3}, {%4,%5,%6,%7}, {%8,%9}, {%0,%1,%2,%3};"
                 : "+f"(d[0]), "+f"(d[1]), "+f"(d[2]), "+f"(d[3])
                 : "r"(a0), "r"(a1), "r"(a2), "r"(a3), "r"(b0), "r"(b1));
}

// Tile format ("kfmt"), per 64x64 tile:
//   word(row, k) = (ks*64 + row)*8 + pos,  ks = k>>3, kin = k&7
//   pos = perm(kin) ^ sw,  perm: [k0,k4,k1,k5,k2,k6,k3,k7],
//   sw = 4*(((row>>2) ^ (ks>>2)) & 1)      (16B XOR swizzle)
// Fragment (kin = t, t+4) = LDS.64 at word 2t^sw. STS.128 stores and LDS.64
// fragment loads are both bank-conflict-free under this swizzle.

// smem word offsets (each tile = 4096 words = 16KB)
#define W_KHI 0
#define W_KLO 4096
#define W_VT  8192
#define W_PS  12288
#define SMEM_WORDS 16384   // 64 KB

// Split-load a 64x64 fp32 tile (row-major, stride 64) into hi/lo kfmt tiles.
// 128 threads: r = tid>>1 (row), kh = tid&1 selects ksteps {0..3} or {4..7}.
__device__ __forceinline__ void load_kfmt_split(const float* __restrict__ src,
                                                uint32_t* __restrict__ smw,
                                                int whi, int wlo, int tid)
{
    const int r = tid >> 1, kh = tid & 1;
    #pragma unroll
    for (int j = 0; j < 4; j++) {
        const int ks = kh * 4 + j;
        float4 a = *(const float4*)(src + (size_t)r * DK_ + ks * 8);
        float4 b = *(const float4*)(src + (size_t)r * DK_ + ks * 8 + 4);
        float x[8] = {a.x, a.y, a.z, a.w, b.x, b.y, b.z, b.w};
        uint32_t h[8], l[8];
        #pragma unroll
        for (int e = 0; e < 8; e++) {
            h[e] = __float_as_uint(x[e]) & 0xFFFFE000u;          // exact tf32 hi
            l[e] = f2tf32(x[e] - __uint_as_float(h[e]));
        }
        const int sw = 4 * (((r >> 2) ^ (ks >> 2)) & 1);
        const uint32_t base = (uint32_t)((ks * 64 + r) * 8);
        *(uint4*)(smw + whi + base + (0 ^ sw)) = make_uint4(h[0], h[4], h[1], h[5]);
        *(uint4*)(smw + whi + base + (4 ^ sw)) = make_uint4(h[2], h[6], h[3], h[7]);
        *(uint4*)(smw + wlo + base + (0 ^ sw)) = make_uint4(l[0], l[4], l[1], l[5]);
        *(uint4*)(smw + wlo + base + (4 ^ sw)) = make_uint4(l[2], l[6], l[3], l[7]);
    }
}

// ===========================================================================
// Tensor-core flash attention: CTA = (b, h, 64 q-rows), 128 threads / 4 warps.
// Q fragments live in registers for the whole s-loop.
// QK = Qhi*Khi + Qlo*Khi + Qhi*Klo (split tf32); PV = single tf32.
// ===========================================================================
__global__ void __launch_bounds__(128, 2) attn_mma_kernel()
{
    extern __shared__ uint32_t smw[];

    const int tid  = threadIdx.x;
    const int lane = tid & 31;
    const int w    = tid >> 5;
    const int g    = lane >> 2;
    const int t    = lane & 3;
    const int g2   = (g >> 2) & 1;
    const int row0 = w * 16 + g;
    const int offA = 2 * t ^ (4 * g2);   // frag word offset for rows with row>>2 parity g2

    const int q0 = blockIdx.x * QROWS;
    const int h  = blockIdx.y;
    const int b  = blockIdx.z;
    const float* __restrict__ Qb = g_Qh + ((size_t)(b * H_ + h) * S_) * DK_;
    const float* __restrict__ Kb = g_Kh + ((size_t)(b * H_ + h) * S_) * DK_;
    const float* __restrict__ Vb = g_Vh + ((size_t)(b * H_ + h) * S_) * DK_;

    // --- Prologue: stage Q through KHI/KLO, build register-resident fragments
    load_kfmt_split(Qb + (size_t)q0 * DK_, smw, W_KHI, W_KLO, tid);
    __syncthreads();

    uint2 qh0[8], qh1[8], ql0[8], ql1[8];
    #pragma unroll
    for (int ks = 0; ks < 8; ks++) {
        const int off = offA ^ (4 * ((ks >> 2) & 1));
        qh0[ks] = *(const uint2*)(smw + W_KHI + (ks * 64 + row0) * 8 + off);
        qh1[ks] = *(const uint2*)(smw + W_KHI + (ks * 64 + row0 + 8) * 8 + off);
        ql0[ks] = *(const uint2*)(smw + W_KLO + (ks * 64 + row0) * 8 + off);
        ql1[ks] = *(const uint2*)(smw + W_KLO + (ks * 64 + row0 + 8) * 8 + off);
    }
    __syncthreads();

    float o[8][4];
    #pragma unroll
    for (int nt = 0; nt < 8; nt++)
        #pragma unroll
        for (int j = 0; j < 4; j++) o[nt][j] = 0.f;
    float mrun[2] = {-1e30f, -1e30f}, lrun[2] = {0.f, 0.f};
    const float Cc = 0.125f * 1.4426950408889634f;

    // P-store permuted positions for cols 2t, 2t+1
    const int pe = ((2 * t) & 3) * 2 + (t >> 1);
    const int po = ((2 * t + 1) & 3) * 2 + ((2 * t + 1) >> 2);

    const int vdk = tid & 63, vsh = tid >> 6;   // V-loader assignment

    for (int it = 0; it < S_ / STILE; it++) {
        const int s0 = it * STILE;

        // --- K tile: split hi/lo, vectorized kfmt stores ---
        load_kfmt_split(Kb + (size_t)s0 * DK_, smw, W_KHI, W_KLO, tid);

        // --- V tile: coalesced column gather -> transposed kfmt (single tf32)
        #pragma unroll
        for (int j = 0; j < 4; j++) {
            const int sc = vsh * 4 + j;
            float x[8];
            #pragma unroll
            for (int si = 0; si < 8; si++)
                x[si] = Vb[(size_t)(s0 + sc * 8 + si) * DK_ + vdk];
            uint32_t v[8];
            #pragma unroll
            for (int e = 0; e < 8; e++) v[e] = f2tf32(x[e]);
            const int sw = 4 * (((vdk >> 2) ^ (sc >> 2)) & 1);
            const uint32_t base = (uint32_t)((sc * 64 + vdk) * 8);
            *(uint4*)(smw + W_VT + base + (0 ^ sw)) = make_uint4(v[0], v[4], v[1], v[5]);
            *(uint4*)(smw + W_VT + base + (4 ^ sw)) = make_uint4(v[2], v[6], v[3], v[7]);
        }
        __syncthreads();

        // --- QK: split tf32, Q frags from registers ---
        float accS[8][4];
        #pragma unroll
        for (int nt = 0; nt < 8; nt++)
            #pragma unroll
            for (int j = 0; j < 4; j++) accS[nt][j] = 0.f;

        #pragma unroll
        for (int ks = 0; ks < 8; ks++) {
            const int off = offA ^ (4 * ((ks >> 2) & 1));
            #pragma unroll
            for (int nt = 0; nt < 8; nt++) {
                const uint32_t ba = (uint32_t)((ks * 64 + nt * 8 + g) * 8 + off);
                uint2 bh = *(const uint2*)(smw + W_KHI + ba);
                uint2 bl = *(const uint2*)(smw + W_KLO + ba);
                mma8(accS[nt], qh0[ks].x, qh1[ks].x, qh0[ks].y, qh1[ks].y, bh.x, bh.y);
                mma8(accS[nt], ql0[ks].x, ql1[ks].x, ql0[ks].y, ql1[ks].y, bh.x, bh.y);
                mma8(accS[nt], qh0[ks].x, qh1[ks].x, qh0[ks].y, qh1[ks].y, bl.x, bl.y);
            }
        }

        // --- Online softmax; write P into PS (kfmt) ---
        #pragma unroll
        for (int j = 0; j < 2; j++) {
            float m = -1e30f;
            #pragma unroll
            for (int nt = 0; nt < 8; nt++)
                m = fmaxf(m, fmaxf(accS[nt][2 * j], accS[nt][2 * j + 1]));
            m = fmaxf(m, __shfl_xor_sync(0xffffffffu, m, 1));
            m = fmaxf(m, __shfl_xor_sync(0xffffffffu, m, 2));

            float mnew = fmaxf(mrun[j], m);
            float scl  = exp2f((mrun[j] - mnew) * Cc);
            mrun[j] = mnew;

            const int prow = row0 + 8 * j;
            float sum = 0.f;
            #pragma unroll
            for (int nt = 0; nt < 8; nt++) {
                float p0 = exp2f((accS[nt][2 * j]     - mnew) * Cc);
                float p1 = exp2f((accS[nt][2 * j + 1] - mnew) * Cc);
                sum += p0 + p1;
                const int sw = 4 * ((g2 ^ (nt >> 2)) & 1);
                const uint32_t base = (uint32_t)((nt * 64 + prow) * 8);
                smw[W_PS + base + (pe ^ sw)] = f2tf32(p0);
                smw[W_PS + base + (po ^ sw)] = f2tf32(p1);
                o[nt][2 * j]     *= scl;
                o[nt][2 * j + 1] *= scl;
            }
            sum += __shfl_xor_sync(0xffffffffu, sum, 1);
            sum += __shfl_xor_sync(0xffffffffu, sum, 2);
            lrun[j] = lrun[j] * scl + sum;
        }
        __syncthreads();

        // --- PV: O += P @ V (single tf32) ---
        #pragma unroll
        for (int ks = 0; ks < 8; ks++) {
            const int off = offA ^ (4 * ((ks >> 2) & 1));
            uint2 p0 = *(const uint2*)(smw + W_PS + (ks * 64 + row0) * 8 + off);
            uint2 p1 = *(const uint2*)(smw + W_PS + (ks * 64 + row0 + 8) * 8 + off);
            #pragma unroll
            for (int nt = 0; nt < 8; nt++) {
                uint2 bv = *(const uint2*)(smw + W_VT + (ks * 64 + nt * 8 + g) * 8 + off);
                mma8(o[nt], p0.x, p1.x, p0.y, p1.y, bv.x, bv.y);
            }
        }
        __syncthreads();   // protect tiles before next iteration overwrites
    }

    // --- Epilogue: normalize, write head-concat layout ---
    #pragma unroll
    for (int j = 0; j < 2; j++) {
        float inv = 1.f / lrun[j];
        int r = row0 + 8 * j;
        float* dst = g_Oc + (size_t)(b * S_ + q0 + r) * D_ + h * DK_;
        #pragma unroll
        for (int nt = 0; nt < 8; nt++) {
            float2 v = make_float2(o[nt][2 * j] * inv, o[nt][2 * j + 1] * inv);
            *(float2*)(dst + nt * 8 + t * 2) = v;
        }
    }
}

// ---------------------------------------------------------------------------
// Projection: Y[b,h,s,k] = sum_d X[b,s,d] * W[h,d,k]   (SIMT fp32)
// ---------------------------------------------------------------------------
__global__ __launch_bounds__(256) void proj_kernel(const float* __restrict__ X,
                                                   const float* __restrict__ W,
                                                   int which)
{
    float* __restrict__ Y = (which == 0) ? g_Qh : (which == 1) ? g_Kh : g_Vh;

    __shared__ float As[64][36];
    __shared__ float Bs[32][68];

    const int h  = blockIdx.x;
    const int m0 = blockIdx.y * 64;
    const int tid = threadIdx.x;
    const int tx = tid & 15, ty = tid >> 4;

    const float* __restrict__ Wh = W + (size_t)h * (D_ * DK_);

    float acc[4][4] = {};

    for (int k0 = 0; k0 < D_; k0 += 32) {
        {
            int f = tid;
            #pragma unroll
            for (int it = 0; it < 2; it++, f += 256) {
                int r = f >> 3, c4 = (f & 7) << 2;
                *(float4*)&As[r][c4] = *(const float4*)(X + (size_t)(m0 + r) * D_ + k0 + c4);
            }
        }
        {
            int f = tid;
            #pragma unroll
            for (int it = 0; it < 2; it++, f += 256) {
                int c = f >> 4, k4 = (f & 15) << 2;
                *(float4*)&Bs[c][k4] = *(const float4*)(Wh + (size_t)(k0 + c) * DK_ + k4);
            }
        }
        __syncthreads();

        #pragma unroll
        for (int kk = 0; kk < 32; kk += 4) {
            float4 a[4];
            #pragma unroll
            for (int i = 0; i < 4; i++) a[i] = *(const float4*)&As[ty * 4 + i][kk];
            #pragma unroll
            for (int tq = 0; tq < 4; tq++) {
                float4 b4 = *(const float4*)&Bs[kk + tq][tx * 4];
                #pragma unroll
                for (int i = 0; i < 4; i++) {
                    float av = comp4(a[i], tq);
                    acc[i][0] += av * b4.x;
                    acc[i][1] += av * b4.y;
                    acc[i][2] += av * b4.z;
                    acc[i][3] += av * b4.w;
                }
            }
        }
        __syncthreads();
    }

    #pragma unroll
    for (int i = 0; i < 4; i++) {
        int m = m0 + ty * 4 + i;
        int b = m / S_, s = m % S_;
        float4 v = make_float4(acc[i][0], acc[i][1], acc[i][2], acc[i][3]);
        *(float4*)(Y + ((size_t)((b * H_ + h) * S_ + s)) * DK_ + tx * 4) = v;
    }
}

// ---------------------------------------------------------------------------
// Output projection: out[m, n] = sum_d Oc[m, d] * WO[d, n]  (SIMT fp32)
// ---------------------------------------------------------------------------
__global__ __launch_bounds__(256) void gemm_out_kernel(const float* __restrict__ WO,
                                                       float* __restrict__ out)
{
    __shared__ float As[64][36];
    __shared__ float Bs[32][68];

    const int n0 = blockIdx.x * 64;
    const int m0 = blockIdx.y * 64;
    const int tid = threadIdx.x;
    const int tx = tid & 15, ty = tid >> 4;

    float acc[4][4] = {};

    for (int k0 = 0; k0 < D_; k0 += 32) {
        {
            int f = tid;
            #pragma unroll
            for (int it = 0; it < 2; it++, f += 256) {
                int r = f >> 3, c4 = (f & 7) << 2;
                *(float4*)&As[r][c4] = *(const float4*)(g_Oc + (size_t)(m0 + r) * D_ + k0 + c4);
            }
        }
        {
            int f = tid;
            #pragma unroll
            for (int it = 0; it < 2; it++, f += 256) {
                int c = f >> 4, k4 = (f & 15) << 2;
                *(float4*)&Bs[c][k4] = *(const float4*)(WO + (size_t)(k0 + c) * D_ + n0 + k4);
            }
        }
        __syncthreads();

        #pragma unroll
        for (int kk = 0; kk < 32; kk += 4) {
            float4 a[4];
            #pragma unroll
            for (int i = 0; i < 4; i++) a[i] = *(const float4*)&As[ty * 4 + i][kk];
            #pragma unroll
            for (int tq = 0; tq < 4; tq++) {
                float4 b4 = *(const float4*)&Bs[kk + tq][tx * 4];
                #pragma unroll
                for (int i = 0; i < 4; i++) {
                    float av = comp4(a[i], tq);
                    acc[i][0] += av * b4.x;
                    acc[i][1] += av * b4.y;
                    acc[i][2] += av * b4.z;
                    acc[i][3] += av * b4.w;
                }
            }
        }
        __syncthreads();
    }

    #pragma unroll
    for (int i = 0; i < 4; i++) {
        int m = m0 + ty * 4 + i;
        float4 v = make_float4(acc[i][0], acc[i][1], acc[i][2], acc[i][3]);
        *(float4*)(out + (size_t)m * D_ + n0 + tx * 4) = v;
    }
}

// ---------------------------------------------------------------------------
extern "C" void kernel_launch(void* const* d_in, const int* in_sizes, int n_in,
                              void* d_out, int out_size)
{
    const float* Q  = (const float*)d_in[0];
    const float* K  = (const float*)d_in[1];
    const float* V  = (const float*)d_in[2];
    const float* WQ = (const float*)d_in[3];
    const float* WK = (const float*)d_in[4];
    const float* WV = (const float*)d_in[5];
    const float* WO = (const float*)d_in[6];
    float* out = (float*)d_out;

    dim3 pgrid(H_, (B_ * S_) / 64);
    proj_kernel<<<pgrid, 256>>>(Q, WQ, 0);
    proj_kernel<<<pgrid, 256>>>(K, WK, 1);
    proj_kernel<<<pgrid, 256>>>(V, WV, 2);

    size_t smem = SMEM_WORDS * sizeof(uint32_t);   // 64 KB
    cudaFuncSetAttribute(attn_mma_kernel,
                         cudaFuncAttributeMaxDynamicSharedMemorySize, (int)smem);
    attn_mma_kernel<<<dim3(S_ / QROWS, H_, B_), 128, smem>>>();

    gemm_out_kernel<<<dim3(D_ / 64, (B_ * S_) / 64), 256>>>(WO, out);
}

// round 7
// speedup vs baseline: 1.5127x; 1.0700x over previous
#include <cuda_runtime.h>
#include <cstdint>

#define B_   4
#define S_   2048
#define D_   512
#define H_   8
#define DK_  64
#define QROWS 64
#define STILE 64

// Scratch (allocation-free: __device__ globals)
__device__ float g_Qh[B_*H_*S_*DK_];
__device__ float g_Kh[B_*H_*S_*DK_];
__device__ float g_Vh[B_*H_*S_*DK_];
__device__ float g_Oc[B_*S_*D_];     // attention output, head-concat layout [B*S, 512]

__device__ __forceinline__ float comp4(const float4& v, int t) {
    return t == 0 ? v.x : t == 1 ? v.y : t == 2 ? v.z : v.w;
}

// ===========================================================================
// mma.sync tf32 helpers (baseline PTX, works on compute_103 target)
// ===========================================================================
__device__ __forceinline__ uint32_t f2tf32(float x) {
    uint32_t r; asm("cvt.rna.tf32.f32 %0, %1;" : "=r"(r) : "f"(x)); return r;
}
__device__ __forceinline__ void mma8(float* d,
                                     uint32_t a0, uint32_t a1, uint32_t a2, uint32_t a3,
                                     uint32_t b0, uint32_t b1) {
    asm volatile("mma.sync.aligned.m16n8k8.row.col.f32.tf32.tf32.f32 "
                 "{%0,%1,%2,%3}, {%4,%5,%6,%7}, {%8,%9}, {%0,%1,%2,%3};"
                 : "+f"(d[0]), "+f"(d[1]), "+f"(d[2]), "+f"(d[3])
                 : "r"(a0), "r"(a1), "r"(a2), "r"(a3), "r"(b0), "r"(b1));
}

// Tile format ("kfmt"), per 64x64 tile:
//   word(row, k) = (ks*64 + row)*8 + pos,  ks = k>>3, kin = k&7
//   pos = perm(kin) ^ sw,  perm: [k0,k4,k1,k5,k2,k6,k3,k7],
//   sw = 4*(((row>>2) ^ (ks>>2)) & 1)      (16B XOR swizzle)
// Fragment (kin = t, t+4) = LDS.64 at word 2t^sw; conflict-free both ways.

// smem word offsets (each tile = 4096 words = 16KB)
#define W_KHI 0
#define W_KLO 4096
#define W_VT  8192
#define W_PS  12288
#define SMEM_WORDS 16384   // 64 KB

// Split-load a 64x64 fp32 tile (row-major, given stride) into hi/lo kfmt.
__device__ __forceinline__ void load_kfmt_split(const float* __restrict__ src,
                                                uint32_t* __restrict__ smw,
                                                int whi, int wlo, int tid, int stride)
{
    const int r = tid >> 1, kh = tid & 1;
    #pragma unroll
    for (int j = 0; j < 4; j++) {
        const int ks = kh * 4 + j;
        float4 a = *(const float4*)(src + (size_t)r * stride + ks * 8);
        float4 b = *(const float4*)(src + (size_t)r * stride + ks * 8 + 4);
        float x[8] = {a.x, a.y, a.z, a.w, b.x, b.y, b.z, b.w};
        uint32_t h[8], l[8];
        #pragma unroll
        for (int e = 0; e < 8; e++) {
            h[e] = __float_as_uint(x[e]) & 0xFFFFE000u;          // exact tf32 hi
            l[e] = f2tf32(x[e] - __uint_as_float(h[e]));
        }
        const int sw = 4 * (((r >> 2) ^ (ks >> 2)) & 1);
        const uint32_t base = (uint32_t)((ks * 64 + r) * 8);
        *(uint4*)(smw + whi + base + (0 ^ sw)) = make_uint4(h[0], h[4], h[1], h[5]);
        *(uint4*)(smw + whi + base + (4 ^ sw)) = make_uint4(h[2], h[6], h[3], h[7]);
        *(uint4*)(smw + wlo + base + (0 ^ sw)) = make_uint4(l[0], l[4], l[1], l[5]);
        *(uint4*)(smw + wlo + base + (4 ^ sw)) = make_uint4(l[2], l[6], l[3], l[7]);
    }
}

// Single-precision (rna tf32) variant.
__device__ __forceinline__ void load_kfmt_single(const float* __restrict__ src,
                                                 uint32_t* __restrict__ smw,
                                                 int whi, int tid, int stride)
{
    const int r = tid >> 1, kh = tid & 1;
    #pragma unroll
    for (int j = 0; j < 4; j++) {
        const int ks = kh * 4 + j;
        float4 a = *(const float4*)(src + (size_t)r * stride + ks * 8);
        float4 b = *(const float4*)(src + (size_t)r * stride + ks * 8 + 4);
        float x[8] = {a.x, a.y, a.z, a.w, b.x, b.y, b.z, b.w};
        uint32_t h[8];
        #pragma unroll
        for (int e = 0; e < 8; e++) h[e] = f2tf32(x[e]);
        const int sw = 4 * (((r >> 2) ^ (ks >> 2)) & 1);
        const uint32_t base = (uint32_t)((ks * 64 + r) * 8);
        *(uint4*)(smw + whi + base + (0 ^ sw)) = make_uint4(h[0], h[4], h[1], h[5]);
        *(uint4*)(smw + whi + base + (4 ^ sw)) = make_uint4(h[2], h[6], h[3], h[7]);
    }
}

// Transposed B loader: kfmt row = n (0..63), k from source rows.
// B tile element (n, k) = bsrc[k * ldb + n]; coalesced over n.
__device__ __forceinline__ void load_kfmt_splitT(const float* __restrict__ bsrc,
                                                 int ldb, uint32_t* __restrict__ smw,
                                                 int whi, int wlo, int tid)
{
    const int n = tid & 63, kh = tid >> 6;
    #pragma unroll
    for (int j = 0; j < 4; j++) {
        const int ks = kh * 4 + j;
        float x[8];
        #pragma unroll
        for (int si = 0; si < 8; si++)
            x[si] = bsrc[(size_t)(ks * 8 + si) * ldb + n];
        uint32_t h[8], l[8];
        #pragma unroll
        for (int e = 0; e < 8; e++) {
            h[e] = __float_as_uint(x[e]) & 0xFFFFE000u;
            l[e] = f2tf32(x[e] - __uint_as_float(h[e]));
        }
        const int sw = 4 * (((n >> 2) ^ (ks >> 2)) & 1);
        const uint32_t base = (uint32_t)((ks * 64 + n) * 8);
        *(uint4*)(smw + whi + base + (0 ^ sw)) = make_uint4(h[0], h[4], h[1], h[5]);
        *(uint4*)(smw + whi + base + (4 ^ sw)) = make_uint4(h[2], h[6], h[3], h[7]);
        *(uint4*)(smw + wlo + base + (0 ^ sw)) = make_uint4(l[0], l[4], l[1], l[5]);
        *(uint4*)(smw + wlo + base + (4 ^ sw)) = make_uint4(l[2], l[6], l[3], l[7]);
    }
}

__device__ __forceinline__ void load_kfmt_singleT(const float* __restrict__ bsrc,
                                                  int ldb, uint32_t* __restrict__ smw,
                                                  int whi, int tid)
{
    const int n = tid & 63, kh = tid >> 6;
    #pragma unroll
    for (int j = 0; j < 4; j++) {
        const int ks = kh * 4 + j;
        float x[8];
        #pragma unroll
        for (int si = 0; si < 8; si++)
            x[si] = bsrc[(size_t)(ks * 8 + si) * ldb + n];
        uint32_t h[8];
        #pragma unroll
        for (int e = 0; e < 8; e++) h[e] = f2tf32(x[e]);
        const int sw = 4 * (((n >> 2) ^ (ks >> 2)) & 1);
        const uint32_t base = (uint32_t)((ks * 64 + n) * 8);
        *(uint4*)(smw + whi + base + (0 ^ sw)) = make_uint4(h[0], h[4], h[1], h[5]);
        *(uint4*)(smw + whi + base + (4 ^ sw)) = make_uint4(h[2], h[6], h[3], h[7]);
    }
}

// One 64x64x64 MMA chunk: acc += A_tile @ B_tile^T (kfmt tiles in smem).
// split: 3-term (AhiBhi + AloBhi + AhiBlo); else 1-term.
__device__ __forceinline__ void mma_chunk(const uint32_t* __restrict__ smw,
                                          int wAhi, int wAlo, int wBhi, int wBlo,
                                          int row0, int g, int offA, bool split,
                                          float acc[8][4])
{
    #pragma unroll
    for (int ks = 0; ks < 8; ks++) {
        const int off = offA ^ (4 * ((ks >> 2) & 1));
        uint2 ah0 = *(const uint2*)(smw + wAhi + (ks * 64 + row0) * 8 + off);
        uint2 ah1 = *(const uint2*)(smw + wAhi + (ks * 64 + row0 + 8) * 8 + off);
        uint2 al0, al1;
        if (split) {
            al0 = *(const uint2*)(smw + wAlo + (ks * 64 + row0) * 8 + off);
            al1 = *(const uint2*)(smw + wAlo + (ks * 64 + row0 + 8) * 8 + off);
        }
        #pragma unroll
        for (int nt = 0; nt < 8; nt++) {
            const uint32_t ba = (uint32_t)((ks * 64 + nt * 8 + g) * 8 + off);
            uint2 bh = *(const uint2*)(smw + wBhi + ba);
            mma8(acc[nt], ah0.x, ah1.x, ah0.y, ah1.y, bh.x, bh.y);
            if (split) {
                uint2 bl = *(const uint2*)(smw + wBlo + ba);
                mma8(acc[nt], al0.x, al1.x, al0.y, al1.y, bh.x, bh.y);
                mma8(acc[nt], ah0.x, ah1.x, ah0.y, ah1.y, bl.x, bl.y);
            }
        }
    }
}

// ===========================================================================
// Projection GEMM (tensor): Y[b,h,s,:] = X[b,s,:] @ W[h]  (per-head N=64)
// grid = (H, 128 m-tiles), 128 thr. split=1 for Q/K, 0 for V.
// ===========================================================================
__global__ void __launch_bounds__(128, 2) proj_mma_kernel(const float* __restrict__ X,
                                                          const float* __restrict__ W,
                                                          int which, int split)
{
    extern __shared__ uint32_t smw[];
    float* __restrict__ Y = (which == 0) ? g_Qh : (which == 1) ? g_Kh : g_Vh;

    const int tid  = threadIdx.x;
    const int lane = tid & 31;
    const int w    = tid >> 5;
    const int g    = lane >> 2;
    const int t    = lane & 3;
    const int row0 = w * 16 + g;
    const int offA = 2 * t ^ (4 * ((g >> 2) & 1));

    const int h  = blockIdx.x;
    const int m0 = blockIdx.y * 64;
    const float* __restrict__ Wh = W + (size_t)h * (D_ * DK_);

    float acc[8][4];
    #pragma unroll
    for (int nt = 0; nt < 8; nt++)
        #pragma unroll
        for (int j = 0; j < 4; j++) acc[nt][j] = 0.f;

    for (int k0 = 0; k0 < D_; k0 += 64) {
        if (split) {
            load_kfmt_split(X + (size_t)m0 * D_ + k0, smw, 0, 4096, tid, D_);
            load_kfmt_splitT(Wh + (size_t)k0 * DK_, DK_, smw, 8192, 12288, tid);
        } else {
            load_kfmt_single(X + (size_t)m0 * D_ + k0, smw, 0, tid, D_);
            load_kfmt_singleT(Wh + (size_t)k0 * DK_, DK_, smw, 4096, tid);
        }
        __syncthreads();
        if (split) mma_chunk(smw, 0, 4096, 8192, 12288, row0, g, offA, true,  acc);
        else       mma_chunk(smw, 0, 0,    4096, 0,     row0, g, offA, false, acc);
        __syncthreads();
    }

    #pragma unroll
    for (int j = 0; j < 2; j++) {
        const int m = m0 + row0 + 8 * j;
        const int b = m >> 11, s = m & 2047;
        float* dst = Y + ((size_t)((b * H_ + h) * S_ + s)) * DK_;
        #pragma unroll
        for (int nt = 0; nt < 8; nt++)
            *(float2*)(dst + nt * 8 + t * 2) = make_float2(acc[nt][2 * j], acc[nt][2 * j + 1]);
    }
}

// ===========================================================================
// Output GEMM (tensor, single tf32): out = Oc[8192,512] @ WO[512,512]
// grid = (8 n-tiles, 128 m-tiles), 128 thr.
// ===========================================================================
__global__ void __launch_bounds__(128, 2) out_mma_kernel(const float* __restrict__ WO,
                                                         float* __restrict__ out)
{
    extern __shared__ uint32_t smw[];

    const int tid  = threadIdx.x;
    const int lane = tid & 31;
    const int w    = tid >> 5;
    const int g    = lane >> 2;
    const int t    = lane & 3;
    const int row0 = w * 16 + g;
    const int offA = 2 * t ^ (4 * ((g >> 2) & 1));

    const int n0 = blockIdx.x * 64;
    const int m0 = blockIdx.y * 64;

    float acc[8][4];
    #pragma unroll
    for (int nt = 0; nt < 8; nt++)
        #pragma unroll
        for (int j = 0; j < 4; j++) acc[nt][j] = 0.f;

    for (int k0 = 0; k0 < D_; k0 += 64) {
        load_kfmt_single(g_Oc + (size_t)m0 * D_ + k0, smw, 0, tid, D_);
        load_kfmt_singleT(WO + (size_t)k0 * D_ + n0, D_, smw, 4096, tid);
        __syncthreads();
        mma_chunk(smw, 0, 0, 4096, 0, row0, g, offA, false, acc);
        __syncthreads();
    }

    #pragma unroll
    for (int j = 0; j < 2; j++) {
        const int m = m0 + row0 + 8 * j;
        float* dst = out + (size_t)m * D_ + n0;
        #pragma unroll
        for (int nt = 0; nt < 8; nt++)
            *(float2*)(dst + nt * 8 + t * 2) = make_float2(acc[nt][2 * j], acc[nt][2 * j + 1]);
    }
}

// ===========================================================================
// Tensor-core flash attention (unchanged from R5): CTA = (b, h, 64 q-rows).
// ===========================================================================
__global__ void __launch_bounds__(128, 2) attn_mma_kernel()
{
    extern __shared__ uint32_t smw[];

    const int tid  = threadIdx.x;
    const int lane = tid & 31;
    const int w    = tid >> 5;
    const int g    = lane >> 2;
    const int t    = lane & 3;
    const int g2   = (g >> 2) & 1;
    const int row0 = w * 16 + g;
    const int offA = 2 * t ^ (4 * g2);

    const int q0 = blockIdx.x * QROWS;
    const int h  = blockIdx.y;
    const int b  = blockIdx.z;
    const float* __restrict__ Qb = g_Qh + ((size_t)(b * H_ + h) * S_) * DK_;
    const float* __restrict__ Kb = g_Kh + ((size_t)(b * H_ + h) * S_) * DK_;
    const float* __restrict__ Vb = g_Vh + ((size_t)(b * H_ + h) * S_) * DK_;

    load_kfmt_split(Qb + (size_t)q0 * DK_, smw, W_KHI, W_KLO, tid, DK_);
    __syncthreads();

    uint2 qh0[8], qh1[8], ql0[8], ql1[8];
    #pragma unroll
    for (int ks = 0; ks < 8; ks++) {
        const int off = offA ^ (4 * ((ks >> 2) & 1));
        qh0[ks] = *(const uint2*)(smw + W_KHI + (ks * 64 + row0) * 8 + off);
        qh1[ks] = *(const uint2*)(smw + W_KHI + (ks * 64 + row0 + 8) * 8 + off);
        ql0[ks] = *(const uint2*)(smw + W_KLO + (ks * 64 + row0) * 8 + off);
        ql1[ks] = *(const uint2*)(smw + W_KLO + (ks * 64 + row0 + 8) * 8 + off);
    }
    __syncthreads();

    float o[8][4];
    #pragma unroll
    for (int nt = 0; nt < 8; nt++)
        #pragma unroll
        for (int j = 0; j < 4; j++) o[nt][j] = 0.f;
    float mrun[2] = {-1e30f, -1e30f}, lrun[2] = {0.f, 0.f};
    const float Cc = 0.125f * 1.4426950408889634f;

    const int pe = ((2 * t) & 3) * 2 + (t >> 1);
    const int po = ((2 * t + 1) & 3) * 2 + ((2 * t + 1) >> 2);

    const int vdk = tid & 63, vsh = tid >> 6;

    for (int it = 0; it < S_ / STILE; it++) {
        const int s0 = it * STILE;

        load_kfmt_split(Kb + (size_t)s0 * DK_, smw, W_KHI, W_KLO, tid, DK_);

        #pragma unroll
        for (int j = 0; j < 4; j++) {
            const int sc = vsh * 4 + j;
            float x[8];
            #pragma unroll
            for (int si = 0; si < 8; si++)
                x[si] = Vb[(size_t)(s0 + sc * 8 + si) * DK_ + vdk];
            uint32_t v[8];
            #pragma unroll
            for (int e = 0; e < 8; e++) v[e] = f2tf32(x[e]);
            const int sw = 4 * (((vdk >> 2) ^ (sc >> 2)) & 1);
            const uint32_t base = (uint32_t)((sc * 64 + vdk) * 8);
            *(uint4*)(smw + W_VT + base + (0 ^ sw)) = make_uint4(v[0], v[4], v[1], v[5]);
            *(uint4*)(smw + W_VT + base + (4 ^ sw)) = make_uint4(v[2], v[6], v[3], v[7]);
        }
        __syncthreads();

        float accS[8][4];
        #pragma unroll
        for (int nt = 0; nt < 8; nt++)
            #pragma unroll
            for (int j = 0; j < 4; j++) accS[nt][j] = 0.f;

        #pragma unroll
        for (int ks = 0; ks < 8; ks++) {
            const int off = offA ^ (4 * ((ks >> 2) & 1));
            #pragma unroll
            for (int nt = 0; nt < 8; nt++) {
                const uint32_t ba = (uint32_t)((ks * 64 + nt * 8 + g) * 8 + off);
                uint2 bh = *(const uint2*)(smw + W_KHI + ba);
                uint2 bl = *(const uint2*)(smw + W_KLO + ba);
                mma8(accS[nt], qh0[ks].x, qh1[ks].x, qh0[ks].y, qh1[ks].y, bh.x, bh.y);
                mma8(accS[nt], ql0[ks].x, ql1[ks].x, ql0[ks].y, ql1[ks].y, bh.x, bh.y);
                mma8(accS[nt], qh0[ks].x, qh1[ks].x, qh0[ks].y, qh1[ks].y, bl.x, bl.y);
            }
        }

        #pragma unroll
        for (int j = 0; j < 2; j++) {
            float m = -1e30f;
            #pragma unroll
            for (int nt = 0; nt < 8; nt++)
                m = fmaxf(m, fmaxf(accS[nt][2 * j], accS[nt][2 * j + 1]));
            m = fmaxf(m, __shfl_xor_sync(0xffffffffu, m, 1));
            m = fmaxf(m, __shfl_xor_sync(0xffffffffu, m, 2));

            float mnew = fmaxf(mrun[j], m);
            float scl  = exp2f((mrun[j] - mnew) * Cc);
            mrun[j] = mnew;

            const int prow = row0 + 8 * j;
            float sum = 0.f;
            #pragma unroll
            for (int nt = 0; nt < 8; nt++) {
                float p0 = exp2f((accS[nt][2 * j]     - mnew) * Cc);
                float p1 = exp2f((accS[nt][2 * j + 1] - mnew) * Cc);
                sum += p0 + p1;
                const int sw = 4 * ((g2 ^ (nt >> 2)) & 1);
                const uint32_t base = (uint32_t)((nt * 64 + prow) * 8);
                smw[W_PS + base + (pe ^ sw)] = f2tf32(p0);
                smw[W_PS + base + (po ^ sw)] = f2tf32(p1);
                o[nt][2 * j]     *= scl;
                o[nt][2 * j + 1] *= scl;
            }
            sum += __shfl_xor_sync(0xffffffffu, sum, 1);
            sum += __shfl_xor_sync(0xffffffffu, sum, 2);
            lrun[j] = lrun[j] * scl + sum;
        }
        __syncthreads();

        #pragma unroll
        for (int ks = 0; ks < 8; ks++) {
            const int off = offA ^ (4 * ((ks >> 2) & 1));
            uint2 p0 = *(const uint2*)(smw + W_PS + (ks * 64 + row0) * 8 + off);
            uint2 p1 = *(const uint2*)(smw + W_PS + (ks * 64 + row0 + 8) * 8 + off);
            #pragma unroll
            for (int nt = 0; nt < 8; nt++) {
                uint2 bv = *(const uint2*)(smw + W_VT + (ks * 64 + nt * 8 + g) * 8 + off);
                mma8(o[nt], p0.x, p1.x, p0.y, p1.y, bv.x, bv.y);
            }
        }
        __syncthreads();
    }

    #pragma unroll
    for (int j = 0; j < 2; j++) {
        float inv = 1.f / lrun[j];
        int r = row0 + 8 * j;
        float* dst = g_Oc + (size_t)(b * S_ + q0 + r) * D_ + h * DK_;
        #pragma unroll
        for (int nt = 0; nt < 8; nt++) {
            float2 v = make_float2(o[nt][2 * j] * inv, o[nt][2 * j + 1] * inv);
            *(float2*)(dst + nt * 8 + t * 2) = v;
        }
    }
}

// ---------------------------------------------------------------------------
extern "C" void kernel_launch(void* const* d_in, const int* in_sizes, int n_in,
                              void* d_out, int out_size)
{
    const float* Q  = (const float*)d_in[0];
    const float* K  = (const float*)d_in[1];
    const float* V  = (const float*)d_in[2];
    const float* WQ = (const float*)d_in[3];
    const float* WK = (const float*)d_in[4];
    const float* WV = (const float*)d_in[5];
    const float* WO = (const float*)d_in[6];
    float* out = (float*)d_out;

    const size_t smem64 = 65536, smem32 = 32768;
    cudaFuncSetAttribute(proj_mma_kernel, cudaFuncAttributeMaxDynamicSharedMemorySize, (int)smem64);
    cudaFuncSetAttribute(out_mma_kernel,  cudaFuncAttributeMaxDynamicSharedMemorySize, (int)smem32);
    cudaFuncSetAttribute(attn_mma_kernel, cudaFuncAttributeMaxDynamicSharedMemorySize, (int)smem64);

    dim3 pgrid(H_, (B_ * S_) / 64);
    proj_mma_kernel<<<pgrid, 128, smem64>>>(Q, WQ, 0, 1);
    proj_mma_kernel<<<pgrid, 128, smem64>>>(K, WK, 1, 1);
    proj_mma_kernel<<<pgrid, 128, smem32>>>(V, WV, 2, 0);

    attn_mma_kernel<<<dim3(S_ / QROWS, H_, B_), 128, smem64>>>();

    out_mma_kernel<<<dim3(D_ / 64, (B_ * S_) / 64), 128, smem32>>>(WO, out);
}

// round 9
// speedup vs baseline: 1.7850x; 1.1800x over previous
#include <cuda_runtime.h>
#include <cstdint>

#define B_   4
#define S_   2048
#define D_   512
#define H_   8
#define DK_  64

// Scratch (allocation-free: __device__ globals)
__device__ float    g_Oc[B_*S_*D_];          // attention output, head-concat [B*S, 512]
// Pre-formatted kfmt tiles: [(b*H+h)*32 + s_tile] * 4096 words
__device__ uint32_t g_Qhi[B_*H_*S_*DK_];
__device__ uint32_t g_Qlo[B_*H_*S_*DK_];
__device__ uint32_t g_Khi[B_*H_*S_*DK_];
__device__ uint32_t g_Klo[B_*H_*S_*DK_];
__device__ uint32_t g_Vt [B_*H_*S_*DK_];     // transposed (rows = dk, k = s)

// ===========================================================================
// mma.sync tf32 helpers (baseline PTX, works on compute_103 target)
// ===========================================================================
__device__ __forceinline__ uint32_t f2tf32(float x) {
    uint32_t r; asm("cvt.rna.tf32.f32 %0, %1;" : "=r"(r) : "f"(x)); return r;
}
__device__ __forceinline__ void mma8(float* d,
                                     uint32_t a0, uint32_t a1, uint32_t a2, uint32_t a3,
                                     uint32_t b0, uint32_t b1) {
    asm volatile("mma.sync.aligned.m16n8k8.row.col.f32.tf32.tf32.f32 "
                 "{%0,%1,%2,%3}, {%4,%5,%6,%7}, {%8,%9}, {%0,%1,%2,%3};"
                 : "+f"(d[0]), "+f"(d[1]), "+f"(d[2]), "+f"(d[3])
                 : "r"(a0), "r"(a1), "r"(a2), "r"(a3), "r"(b0), "r"(b1));
}
__device__ __forceinline__ void cp16(uint32_t saddr, const void* g) {
    asm volatile("cp.async.cg.shared.global [%0], [%1], 16;" :: "r"(saddr), "l"(g) : "memory");
}
#define CP_COMMIT() asm volatile("cp.async.commit_group;" ::: "memory")
__device__ __forceinline__ uint32_t smem_u32(const void* p) {
    uint32_t a;
    asm("{ .reg .u64 t; cvta.to.shared.u64 t, %1; cvt.u32.u64 %0, t; }" : "=r"(a) : "l"(p));
    return a;
}

// kfmt, per 64x64 tile: word(row,k) = (ks*64+row)*8 + pos(kin)^sw,
//   ks=k>>3, kin=k&7, pos(kin) = (kin&3)*2 + (kin>>2),
//   sw = 4*(((row>>2)^(ks>>2))&1). Fragment (kin=t,t+4) = LDS.64 at 2t^sw.

// ---------------------------------------------------------------------------
// Loaders for GEMM kernels (gmem fp32 -> smem kfmt)
// ---------------------------------------------------------------------------
__device__ __forceinline__ void load_kfmt_split(const float* __restrict__ src,
                                                uint32_t* __restrict__ smw,
                                                int whi, int wlo, int tid, int stride)
{
    const int r = tid >> 1, kh = tid & 1;
    #pragma unroll
    for (int j = 0; j < 4; j++) {
        const int ks = kh * 4 + j;
        float4 a = *(const float4*)(src + (size_t)r * stride + ks * 8);
        float4 b = *(const float4*)(src + (size_t)r * stride + ks * 8 + 4);
        float x[8] = {a.x, a.y, a.z, a.w, b.x, b.y, b.z, b.w};
        uint32_t h[8], l[8];
        #pragma unroll
        for (int e = 0; e < 8; e++) {
            h[e] = __float_as_uint(x[e]) & 0xFFFFE000u;
            l[e] = f2tf32(x[e] - __uint_as_float(h[e]));
        }
        const int sw = 4 * (((r >> 2) ^ (ks >> 2)) & 1);
        const uint32_t base = (uint32_t)((ks * 64 + r) * 8);
        *(uint4*)(smw + whi + base + (0 ^ sw)) = make_uint4(h[0], h[4], h[1], h[5]);
        *(uint4*)(smw + whi + base + (4 ^ sw)) = make_uint4(h[2], h[6], h[3], h[7]);
        *(uint4*)(smw + wlo + base + (0 ^ sw)) = make_uint4(l[0], l[4], l[1], l[5]);
        *(uint4*)(smw + wlo + base + (4 ^ sw)) = make_uint4(l[2], l[6], l[3], l[7]);
    }
}
__device__ __forceinline__ void load_kfmt_single(const float* __restrict__ src,
                                                 uint32_t* __restrict__ smw,
                                                 int whi, int tid, int stride)
{
    const int r = tid >> 1, kh = tid & 1;
    #pragma unroll
    for (int j = 0; j < 4; j++) {
        const int ks = kh * 4 + j;
        float4 a = *(const float4*)(src + (size_t)r * stride + ks * 8);
        float4 b = *(const float4*)(src + (size_t)r * stride + ks * 8 + 4);
        float x[8] = {a.x, a.y, a.z, a.w, b.x, b.y, b.z, b.w};
        uint32_t h[8];
        #pragma unroll
        for (int e = 0; e < 8; e++) h[e] = f2tf32(x[e]);
        const int sw = 4 * (((r >> 2) ^ (ks >> 2)) & 1);
        const uint32_t base = (uint32_t)((ks * 64 + r) * 8);
        *(uint4*)(smw + whi + base + (0 ^ sw)) = make_uint4(h[0], h[4], h[1], h[5]);
        *(uint4*)(smw + whi + base + (4 ^ sw)) = make_uint4(h[2], h[6], h[3], h[7]);
    }
}
__device__ __forceinline__ void load_kfmt_splitT(const float* __restrict__ bsrc,
                                                 int ldb, uint32_t* __restrict__ smw,
                                                 int whi, int wlo, int tid)
{
    const int n = tid & 63, kh = tid >> 6;
    #pragma unroll
    for (int j = 0; j < 4; j++) {
        const int ks = kh * 4 + j;
        float x[8];
        #pragma unroll
        for (int si = 0; si < 8; si++)
            x[si] = bsrc[(size_t)(ks * 8 + si) * ldb + n];
        uint32_t h[8], l[8];
        #pragma unroll
        for (int e = 0; e < 8; e++) {
            h[e] = __float_as_uint(x[e]) & 0xFFFFE000u;
            l[e] = f2tf32(x[e] - __uint_as_float(h[e]));
        }
        const int sw = 4 * (((n >> 2) ^ (ks >> 2)) & 1);
        const uint32_t base = (uint32_t)((ks * 64 + n) * 8);
        *(uint4*)(smw + whi + base + (0 ^ sw)) = make_uint4(h[0], h[4], h[1], h[5]);
        *(uint4*)(smw + whi + base + (4 ^ sw)) = make_uint4(h[2], h[6], h[3], h[7]);
        *(uint4*)(smw + wlo + base + (0 ^ sw)) = make_uint4(l[0], l[4], l[1], l[5]);
        *(uint4*)(smw + wlo + base + (4 ^ sw)) = make_uint4(l[2], l[6], l[3], l[7]);
    }
}
__device__ __forceinline__ void load_kfmt_singleT(const float* __restrict__ bsrc,
                                                  int ldb, uint32_t* __restrict__ smw,
                                                  int whi, int tid)
{
    const int n = tid & 63, kh = tid >> 6;
    #pragma unroll
    for (int j = 0; j < 4; j++) {
        const int ks = kh * 4 + j;
        float x[8];
        #pragma unroll
        for (int si = 0; si < 8; si++)
            x[si] = bsrc[(size_t)(ks * 8 + si) * ldb + n];
        uint32_t h[8];
        #pragma unroll
        for (int e = 0; e < 8; e++) h[e] = f2tf32(x[e]);
        const int sw = 4 * (((n >> 2) ^ (ks >> 2)) & 1);
        const uint32_t base = (uint32_t)((ks * 64 + n) * 8);
        *(uint4*)(smw + whi + base + (0 ^ sw)) = make_uint4(h[0], h[4], h[1], h[5]);
        *(uint4*)(smw + whi + base + (4 ^ sw)) = make_uint4(h[2], h[6], h[3], h[7]);
    }
}

// One 64x64x64 MMA chunk (A rows row0/row0+8; B all 64 cols).
__device__ __forceinline__ void mma_chunk(const uint32_t* __restrict__ smw,
                                          int wAhi, int wAlo, int wBhi, int wBlo,
                                          int row0, int g, int offA, bool split,
                                          float acc[8][4])
{
    #pragma unroll
    for (int ks = 0; ks < 8; ks++) {
        const int off = offA ^ (4 * ((ks >> 2) & 1));
        uint2 ah0 = *(const uint2*)(smw + wAhi + (ks * 64 + row0) * 8 + off);
        uint2 ah1 = *(const uint2*)(smw + wAhi + (ks * 64 + row0 + 8) * 8 + off);
        uint2 al0, al1;
        if (split) {
            al0 = *(const uint2*)(smw + wAlo + (ks * 64 + row0) * 8 + off);
            al1 = *(const uint2*)(smw + wAlo + (ks * 64 + row0 + 8) * 8 + off);
        }
        #pragma unroll
        for (int nt = 0; nt < 8; nt++) {
            const uint32_t ba = (uint32_t)((ks * 64 + nt * 8 + g) * 8 + off);
            uint2 bh = *(const uint2*)(smw + wBhi + ba);
            mma8(acc[nt], ah0.x, ah1.x, ah0.y, ah1.y, bh.x, bh.y);
            if (split) {
                uint2 bl = *(const uint2*)(smw + wBlo + ba);
                mma8(acc[nt], al0.x, al1.x, al0.y, al1.y, bh.x, bh.y);
                mma8(acc[nt], ah0.x, ah1.x, ah0.y, ah1.y, bl.x, bl.y);
            }
        }
    }
}

// ===========================================================================
// Projection GEMM + kfmt epilogue.
// which: 0=Q (split out), 1=K (split out), 2=V (single tf32, transposed out)
// grid = (H, 128 m-tiles), 128 thr.
// ===========================================================================
__global__ void __launch_bounds__(128, 2) proj_mma_kernel(const float* __restrict__ X,
                                                          const float* __restrict__ W,
                                                          int which, int split)
{
    extern __shared__ uint32_t smw[];

    const int tid  = threadIdx.x;
    const int lane = tid & 31;
    const int w    = tid >> 5;
    const int g    = lane >> 2;
    const int t    = lane & 3;
    const int row0 = w * 16 + g;
    const int offA = 2 * t ^ (4 * ((g >> 2) & 1));
    const int pe = ((2 * t) & 3) * 2 + (t >> 1);
    const int po = ((2 * t + 1) & 3) * 2 + ((2 * t + 1) >> 2);

    const int h  = blockIdx.x;
    const int m0 = blockIdx.y * 64;
    const float* __restrict__ Wh = W + (size_t)h * (D_ * DK_);

    float acc[8][4];
    #pragma unroll
    for (int nt = 0; nt < 8; nt++)
        #pragma unroll
        for (int j = 0; j < 4; j++) acc[nt][j] = 0.f;

    for (int k0 = 0; k0 < D_; k0 += 64) {
        if (split) {
            load_kfmt_split(X + (size_t)m0 * D_ + k0, smw, 0, 4096, tid, D_);
            load_kfmt_splitT(Wh + (size_t)k0 * DK_, DK_, smw, 8192, 12288, tid);
        } else {
            load_kfmt_single(X + (size_t)m0 * D_ + k0, smw, 0, tid, D_);
            load_kfmt_singleT(Wh + (size_t)k0 * DK_, DK_, smw, 4096, tid);
        }
        __syncthreads();
        if (split) mma_chunk(smw, 0, 4096, 8192, 12288, row0, g, offA, true,  acc);
        else       mma_chunk(smw, 0, 0,    4096, 0,     row0, g, offA, false, acc);
        __syncthreads();
    }

    const int bb = m0 >> 11, st = (m0 & 2047) >> 6;
    const size_t tbase = ((size_t)(bb * H_ + h) * 32 + st) * 4096;

    if (which != 2) {
        // split epilogue: hi -> smw[0..4096), lo -> smw[4096..8192), kfmt
        #pragma unroll
        for (int j = 0; j < 2; j++) {
            const int r = row0 + 8 * j;
            #pragma unroll
            for (int nt = 0; nt < 8; nt++) {
                float p0 = acc[nt][2 * j], p1 = acc[nt][2 * j + 1];
                uint32_t h0 = __float_as_uint(p0) & 0xFFFFE000u;
                uint32_t h1 = __float_as_uint(p1) & 0xFFFFE000u;
                uint32_t l0 = f2tf32(p0 - __uint_as_float(h0));
                uint32_t l1 = f2tf32(p1 - __uint_as_float(h1));
                const int sw = 4 * ((((r >> 2) ^ (nt >> 2)) & 1));
                const uint32_t base = (uint32_t)((nt * 64 + r) * 8);
                smw[base + (pe ^ sw)] = h0;
                smw[base + (po ^ sw)] = h1;
                smw[4096 + base + (pe ^ sw)] = l0;
                smw[4096 + base + (po ^ sw)] = l1;
            }
        }
        __syncthreads();
        uint32_t* dH = (which == 0 ? g_Qhi : g_Khi) + tbase;
        uint32_t* dL = (which == 0 ? g_Qlo : g_Klo) + tbase;
        const uint4* s4 = (const uint4*)smw;
        for (int i = tid; i < 1024; i += 128) {
            ((uint4*)dH)[i] = s4[i];
            ((uint4*)dL)[i] = s4[1024 + i];
        }
    } else {
        // V epilogue: raw tf32 tile (row=s', col=dk) -> transpose -> kfmt Vt
        #pragma unroll
        for (int j = 0; j < 2; j++) {
            const int r = row0 + 8 * j;
            #pragma unroll
            for (int nt = 0; nt < 8; nt++) {
                smw[r * 64 + nt * 8 + 2 * t]     = f2tf32(acc[nt][2 * j]);
                smw[r * 64 + nt * 8 + 2 * t + 1] = f2tf32(acc[nt][2 * j + 1]);
            }
        }
        __syncthreads();
        {
            const int vdk = tid & 63, vsh = tid >> 6;
            #pragma unroll
            for (int j = 0; j < 4; j++) {
                const int sc = vsh * 4 + j + ((vsh == 1) ? 0 : 0);  // sc in 0..7 via vsh*4+j
                uint32_t v[8];
                #pragma unroll
                for (int si = 0; si < 8; si++)
                    v[si] = smw[(sc * 8 + si) * 64 + vdk];
                const int sw = 4 * (((vdk >> 2) ^ (sc >> 2)) & 1);
                const uint32_t base = (uint32_t)((sc * 64 + vdk) * 8);
                *(uint4*)(smw + 4096 + base + (0 ^ sw)) = make_uint4(v[0], v[4], v[1], v[5]);
                *(uint4*)(smw + 4096 + base + (4 ^ sw)) = make_uint4(v[2], v[6], v[3], v[7]);
            }
        }
        __syncthreads();
        uint32_t* dV = g_Vt + tbase;
        const uint4* s4 = (const uint4*)(smw + 4096);
        for (int i = tid; i < 1024; i += 128)
            ((uint4*)dV)[i] = s4[i];
    }
}

// ===========================================================================
// Output GEMM (tensor, single tf32): out = Oc[8192,512] @ WO[512,512]
// ===========================================================================
__global__ void __launch_bounds__(128, 2) out_mma_kernel(const float* __restrict__ WO,
                                                         float* __restrict__ out)
{
    extern __shared__ uint32_t smw[];

    const int tid  = threadIdx.x;
    const int lane = tid & 31;
    const int w    = tid >> 5;
    const int g    = lane >> 2;
    const int t    = lane & 3;
    const int row0 = w * 16 + g;
    const int offA = 2 * t ^ (4 * ((g >> 2) & 1));

    const int n0 = blockIdx.x * 64;
    const int m0 = blockIdx.y * 64;

    float acc[8][4];
    #pragma unroll
    for (int nt = 0; nt < 8; nt++)
        #pragma unroll
        for (int j = 0; j < 4; j++) acc[nt][j] = 0.f;

    for (int k0 = 0; k0 < D_; k0 += 64) {
        load_kfmt_single(g_Oc + (size_t)m0 * D_ + k0, smw, 0, tid, D_);
        load_kfmt_singleT(WO + (size_t)k0 * D_ + n0, D_, smw, 4096, tid);
        __syncthreads();
        mma_chunk(smw, 0, 0, 4096, 0, row0, g, offA, false, acc);
        __syncthreads();
    }

    #pragma unroll
    for (int j = 0; j < 2; j++) {
        const int m = m0 + row0 + 8 * j;
        float* dst = out + (size_t)m * D_ + n0;
        #pragma unroll
        for (int nt = 0; nt < 8; nt++)
            *(float2*)(dst + nt * 8 + t * 2) = make_float2(acc[nt][2 * j], acc[nt][2 * j + 1]);
    }
}

// ===========================================================================
// Flash attention: CTA = (b, h, 128 q-rows), 256 threads / 8 warps.
// Pre-formatted tiles streamed via double-buffered cp.async.
// smem (words): buf0 [KHI 0 | KLO 4096 | VT 8192], buf1 +12288, PS 24576(x2 tiles)
// ===========================================================================
#define ABUF 12288
#define APS  24576
#define ASMEM_WORDS 32768   // 128 KB

__global__ void __launch_bounds__(256, 1) attn_mma_kernel()
{
    extern __shared__ uint32_t smw[];
    const uint32_t sbase = smem_u32(smw);

    const int tid  = threadIdx.x;
    const int lane = tid & 31;
    const int w    = tid >> 5;            // 0..7
    const int g    = lane >> 2;
    const int t    = lane & 3;
    const int g2   = (g >> 2) & 1;
    const int row0 = w * 16 + g;          // 0..127
    const int offA = 2 * t ^ (4 * g2);
    const int pe = ((2 * t) & 3) * 2 + (t >> 1);
    const int po = ((2 * t + 1) & 3) * 2 + ((2 * t + 1) >> 2);

    const int h  = blockIdx.y;
    const int b  = blockIdx.z;
    const size_t kvbase = ((size_t)(b * H_ + h)) * 32 * 4096;

    // --- prologue: start loading tile 0 into buf 0 ---
    {
        const uint4* sK = (const uint4*)(g_Khi + kvbase);
        const uint4* sL = (const uint4*)(g_Klo + kvbase);
        const uint4* sV = (const uint4*)(g_Vt  + kvbase);
        #pragma unroll
        for (int k = 0; k < 4; k++) {
            const int i = tid + k * 256;
            cp16(sbase + i * 16,          sK + i);
            cp16(sbase + 16384 + i * 16,  sL + i);
            cp16(sbase + 32768 + i * 16,  sV + i);
        }
        CP_COMMIT();
    }

    // --- Q fragments via direct LDG from pre-split kfmt tiles ---
    uint2 qh0[8], qh1[8], ql0[8], ql1[8];
    {
        const int qst = blockIdx.x * 2 + (row0 >> 6);
        const size_t qtb = ((size_t)(b * H_ + h) * 32 + qst) * 4096;
        const int r = row0 & 63;
        #pragma unroll
        for (int ks = 0; ks < 8; ks++) {
            const int off = offA ^ (4 * ((ks >> 2) & 1));
            const size_t i0 = qtb + (ks * 64 + r) * 8 + off;
            const size_t i1 = qtb + (ks * 64 + r + 8) * 8 + off;
            qh0[ks] = *(const uint2*)(g_Qhi + i0);
            qh1[ks] = *(const uint2*)(g_Qhi + i1);
            ql0[ks] = *(const uint2*)(g_Qlo + i0);
            ql1[ks] = *(const uint2*)(g_Qlo + i1);
        }
    }

    float o[8][4];
    #pragma unroll
    for (int nt = 0; nt < 8; nt++)
        #pragma unroll
        for (int j = 0; j < 4; j++) o[nt][j] = 0.f;
    float mrun[2] = {-1e30f, -1e30f}, lrun[2] = {0.f, 0.f};
    const float Cc = 0.125f * 1.4426950408889634f;

    const int ptile = APS + (row0 >> 6) * 4096;   // this warp's P tile
    const int pr    = row0 & 63;

    for (int it = 0; it < 32; it++) {
        const int cur = it & 1;

        if (it < 31) {   // prefetch next tile into other buffer
            const uint32_t db = sbase + (cur ^ 1) * (ABUF * 4);
            const size_t tb = kvbase + (size_t)(it + 1) * 4096;
            const uint4* sK = (const uint4*)(g_Khi + tb);
            const uint4* sL = (const uint4*)(g_Klo + tb);
            const uint4* sV = (const uint4*)(g_Vt  + tb);
            #pragma unroll
            for (int k = 0; k < 4; k++) {
                const int i = tid + k * 256;
                cp16(db + i * 16,          sK + i);
                cp16(db + 16384 + i * 16,  sL + i);
                cp16(db + 32768 + i * 16,  sV + i);
            }
            CP_COMMIT();
            asm volatile("cp.async.wait_group 1;" ::: "memory");
        } else {
            asm volatile("cp.async.wait_group 0;" ::: "memory");
        }
        __syncthreads();    // cur buffer visible to all warps

        const int bk = cur * ABUF;

        // --- QK: split tf32 (3 terms), Q frags from registers ---
        float accS[8][4];
        #pragma unroll
        for (int nt = 0; nt < 8; nt++)
            #pragma unroll
            for (int j = 0; j < 4; j++) accS[nt][j] = 0.f;

        #pragma unroll
        for (int ks = 0; ks < 8; ks++) {
            const int off = offA ^ (4 * ((ks >> 2) & 1));
            #pragma unroll
            for (int nt = 0; nt < 8; nt++) {
                const uint32_t ba = (uint32_t)(bk + (ks * 64 + nt * 8 + g) * 8 + off);
                uint2 bh = *(const uint2*)(smw + ba);
                uint2 bl = *(const uint2*)(smw + 4096 + ba);
                mma8(accS[nt], qh0[ks].x, qh1[ks].x, qh0[ks].y, qh1[ks].y, bh.x, bh.y);
                mma8(accS[nt], ql0[ks].x, ql1[ks].x, ql0[ks].y, ql1[ks].y, bh.x, bh.y);
                mma8(accS[nt], qh0[ks].x, qh1[ks].x, qh0[ks].y, qh1[ks].y, bl.x, bl.y);
            }
        }

        // --- Online softmax; write P (kfmt) into this warp's PS tile ---
        #pragma unroll
        for (int j = 0; j < 2; j++) {
            float m = -1e30f;
            #pragma unroll
            for (int nt = 0; nt < 8; nt++)
                m = fmaxf(m, fmaxf(accS[nt][2 * j], accS[nt][2 * j + 1]));
            m = fmaxf(m, __shfl_xor_sync(0xffffffffu, m, 1));
            m = fmaxf(m, __shfl_xor_sync(0xffffffffu, m, 2));

            float mnew = fmaxf(mrun[j], m);
            float scl  = exp2f((mrun[j] - mnew) * Cc);
            mrun[j] = mnew;

            const int prow = pr + 8 * j;
            float sum = 0.f;
            #pragma unroll
            for (int nt = 0; nt < 8; nt++) {
                float p0 = exp2f((accS[nt][2 * j]     - mnew) * Cc);
                float p1 = exp2f((accS[nt][2 * j + 1] - mnew) * Cc);
                sum += p0 + p1;
                const int sw = 4 * ((g2 ^ (nt >> 2)) & 1);
                const uint32_t base = (uint32_t)(ptile + (nt * 64 + prow) * 8);
                smw[base + (pe ^ sw)] = f2tf32(p0);
                smw[base + (po ^ sw)] = f2tf32(p1);
                o[nt][2 * j]     *= scl;
                o[nt][2 * j + 1] *= scl;
            }
            sum += __shfl_xor_sync(0xffffffffu, sum, 1);
            sum += __shfl_xor_sync(0xffffffffu, sum, 2);
            lrun[j] = lrun[j] * scl + sum;
        }
        __syncwarp();   // P tile is per-warp-private: warp-level visibility only

        // --- PV: O += P @ Vt (single tf32) ---
        #pragma unroll
        for (int ks = 0; ks < 8; ks++) {
            const int off = offA ^ (4 * ((ks >> 2) & 1));
            uint2 p0 = *(const uint2*)(smw + ptile + (ks * 64 + pr) * 8 + off);
            uint2 p1 = *(const uint2*)(smw + ptile + (ks * 64 + pr + 8) * 8 + off);
            #pragma unroll
            for (int nt = 0; nt < 8; nt++) {
                uint2 bv = *(const uint2*)(smw + bk + 8192 + (ks * 64 + nt * 8 + g) * 8 + off);
                mma8(o[nt], p0.x, p1.x, p0.y, p1.y, bv.x, bv.y);
            }
        }
        __syncthreads();   // all warps done with cur before it gets overwritten
    }

    // --- Epilogue: normalize, write head-concat layout ---
    const int q0 = blockIdx.x * 128;
    #pragma unroll
    for (int j = 0; j < 2; j++) {
        float inv = 1.f / lrun[j];
        int r = q0 + row0 + 8 * j;
        float* dst = g_Oc + (size_t)(b * S_ + r) * D_ + h * DK_;
        #pragma unroll
        for (int nt = 0; nt < 8; nt++) {
            float2 v = make_float2(o[nt][2 * j] * inv, o[nt][2 * j + 1] * inv);
            *(float2*)(dst + nt * 8 + t * 2) = v;
        }
    }
}

// ---------------------------------------------------------------------------
// NOTE on PS privacy: each warp reads/writes only rows [w*16, w*16+16) of its
// 64-row PS tile (4 warps per tile, disjoint row ranges; fragment addresses
// touch only rows pr..pr+15). Warp-level sync suffices between P store and PV.
// ---------------------------------------------------------------------------
extern "C" void kernel_launch(void* const* d_in, const int* in_sizes, int n_in,
                              void* d_out, int out_size)
{
    const float* Q  = (const float*)d_in[0];
    const float* K  = (const float*)d_in[1];
    const float* V  = (const float*)d_in[2];
    const float* WQ = (const float*)d_in[3];
    const float* WK = (const float*)d_in[4];
    const float* WV = (const float*)d_in[5];
    const float* WO = (const float*)d_in[6];
    float* out = (float*)d_out;

    const size_t smem64 = 65536, smem32 = 32768;
    const size_t smemA  = (size_t)ASMEM_WORDS * 4;   // 128 KB
    cudaFuncSetAttribute(proj_mma_kernel, cudaFuncAttributeMaxDynamicSharedMemorySize, (int)smem64);
    cudaFuncSetAttribute(out_mma_kernel,  cudaFuncAttributeMaxDynamicSharedMemorySize, (int)smem32);
    cudaFuncSetAttribute(attn_mma_kernel, cudaFuncAttributeMaxDynamicSharedMemorySize, (int)smemA);

    dim3 pgrid(H_, (B_ * S_) / 64);
    proj_mma_kernel<<<pgrid, 128, smem64>>>(Q, WQ, 0, 1);
    proj_mma_kernel<<<pgrid, 128, smem64>>>(K, WK, 1, 1);
    proj_mma_kernel<<<pgrid, 128, smem32>>>(V, WV, 2, 0);

    attn_mma_kernel<<<dim3(S_ / 128, H_, B_), 256, smemA>>>();

    out_mma_kernel<<<dim3(D_ / 64, (B_ * S_) / 64), 128, smem32>>>(WO, out);
}

// round 10
// speedup vs baseline: 1.8447x; 1.0335x over previous
#include <cuda_runtime.h>
#include <cstdint>

#define B_   4
#define S_   2048
#define D_   512
#define H_   8
#define DK_  64

// Scratch (allocation-free: __device__ globals)
__device__ float    g_Oc[B_*S_*D_];          // attention output, head-concat [B*S, 512]
// Pre-formatted kfmt tiles: [(b*H+h)*32 + s_tile] * 4096 words
__device__ uint32_t g_Qhi[B_*H_*S_*DK_];
__device__ uint32_t g_Qlo[B_*H_*S_*DK_];
__device__ uint32_t g_Khi[B_*H_*S_*DK_];
__device__ uint32_t g_Klo[B_*H_*S_*DK_];
__device__ uint32_t g_Vt [B_*H_*S_*DK_];     // transposed (rows = dk, k = s)

// ===========================================================================
// mma.sync tf32 helpers (baseline PTX, works on compute_103 target)
// ===========================================================================
__device__ __forceinline__ uint32_t f2tf32(float x) {
    uint32_t r; asm("cvt.rna.tf32.f32 %0, %1;" : "=r"(r) : "f"(x)); return r;
}
__device__ __forceinline__ void mma8(float* d,
                                     uint32_t a0, uint32_t a1, uint32_t a2, uint32_t a3,
                                     uint32_t b0, uint32_t b1) {
    asm volatile("mma.sync.aligned.m16n8k8.row.col.f32.tf32.tf32.f32 "
                 "{%0,%1,%2,%3}, {%4,%5,%6,%7}, {%8,%9}, {%0,%1,%2,%3};"
                 : "+f"(d[0]), "+f"(d[1]), "+f"(d[2]), "+f"(d[3])
                 : "r"(a0), "r"(a1), "r"(a2), "r"(a3), "r"(b0), "r"(b1));
}
__device__ __forceinline__ void cp16(uint32_t saddr, const void* g) {
    asm volatile("cp.async.cg.shared.global [%0], [%1], 16;" :: "r"(saddr), "l"(g) : "memory");
}
#define CP_COMMIT() asm volatile("cp.async.commit_group;" ::: "memory")
__device__ __forceinline__ uint32_t smem_u32(const void* p) {
    uint32_t a;
    asm("{ .reg .u64 t; cvta.to.shared.u64 t, %1; cvt.u32.u64 %0, t; }" : "=r"(a) : "l"(p));
    return a;
}

// kfmt, per 64x64 tile: word(row,k) = (ks*64+row)*8 + pos(kin)^sw,
//   ks=k>>3, kin=k&7, pos(kin) = (kin&3)*2 + (kin>>2),
//   sw = 4*(((row>>2)^(ks>>2))&1). Fragment (kin=t,t+4) = LDS.64 at 2t^sw.

// ---------------------------------------------------------------------------
// Pipelined loaders: LDG half (stage in regs) + convert/STS half.
// A-side (row-major): thread covers row r = tid>>1, ksteps (tid&1)*4 .. +3.
// B-side (transposed gather): thread covers col n = tid&63, ksteps (tid>>6)*4..+3.
// ---------------------------------------------------------------------------
__device__ __forceinline__ void ldg_rows(const float* __restrict__ src, int tid,
                                         int stride, float4 xa[4], float4 xb[4])
{
    const int r = tid >> 1, kh = tid & 1;
    #pragma unroll
    for (int j = 0; j < 4; j++) {
        const int ks = kh * 4 + j;
        xa[j] = *(const float4*)(src + (size_t)r * stride + ks * 8);
        xb[j] = *(const float4*)(src + (size_t)r * stride + ks * 8 + 4);
    }
}
__device__ __forceinline__ void sts_split(const float4 xa[4], const float4 xb[4],
                                          uint32_t* __restrict__ smw,
                                          int whi, int wlo, int tid)
{
    const int r = tid >> 1, kh = tid & 1;
    #pragma unroll
    for (int j = 0; j < 4; j++) {
        const int ks = kh * 4 + j;
        float x[8] = {xa[j].x, xa[j].y, xa[j].z, xa[j].w,
                      xb[j].x, xb[j].y, xb[j].z, xb[j].w};
        uint32_t h[8], l[8];
        #pragma unroll
        for (int e = 0; e < 8; e++) {
            h[e] = __float_as_uint(x[e]) & 0xFFFFE000u;
            l[e] = f2tf32(x[e] - __uint_as_float(h[e]));
        }
        const int sw = 4 * (((r >> 2) ^ (ks >> 2)) & 1);
        const uint32_t base = (uint32_t)((ks * 64 + r) * 8);
        *(uint4*)(smw + whi + base + (0 ^ sw)) = make_uint4(h[0], h[4], h[1], h[5]);
        *(uint4*)(smw + whi + base + (4 ^ sw)) = make_uint4(h[2], h[6], h[3], h[7]);
        *(uint4*)(smw + wlo + base + (0 ^ sw)) = make_uint4(l[0], l[4], l[1], l[5]);
        *(uint4*)(smw + wlo + base + (4 ^ sw)) = make_uint4(l[2], l[6], l[3], l[7]);
    }
}
__device__ __forceinline__ void sts_single(const float4 xa[4], const float4 xb[4],
                                           uint32_t* __restrict__ smw,
                                           int whi, int tid)
{
    const int r = tid >> 1, kh = tid & 1;
    #pragma unroll
    for (int j = 0; j < 4; j++) {
        const int ks = kh * 4 + j;
        float x[8] = {xa[j].x, xa[j].y, xa[j].z, xa[j].w,
                      xb[j].x, xb[j].y, xb[j].z, xb[j].w};
        uint32_t h[8];
        #pragma unroll
        for (int e = 0; e < 8; e++) h[e] = f2tf32(x[e]);
        const int sw = 4 * (((r >> 2) ^ (ks >> 2)) & 1);
        const uint32_t base = (uint32_t)((ks * 64 + r) * 8);
        *(uint4*)(smw + whi + base + (0 ^ sw)) = make_uint4(h[0], h[4], h[1], h[5]);
        *(uint4*)(smw + whi + base + (4 ^ sw)) = make_uint4(h[2], h[6], h[3], h[7]);
    }
}
__device__ __forceinline__ void ldg_T(const float* __restrict__ bsrc, int ldb,
                                      int tid, float wst[4][8])
{
    const int n = tid & 63, kh = tid >> 6;
    #pragma unroll
    for (int j = 0; j < 4; j++) {
        const int ks = kh * 4 + j;
        #pragma unroll
        for (int si = 0; si < 8; si++)
            wst[j][si] = bsrc[(size_t)(ks * 8 + si) * ldb + n];
    }
}
__device__ __forceinline__ void sts_T_split(const float wst[4][8],
                                            uint32_t* __restrict__ smw,
                                            int whi, int wlo, int tid)
{
    const int n = tid & 63, kh = tid >> 6;
    #pragma unroll
    for (int j = 0; j < 4; j++) {
        const int ks = kh * 4 + j;
        uint32_t h[8], l[8];
        #pragma unroll
        for (int e = 0; e < 8; e++) {
            h[e] = __float_as_uint(wst[j][e]) & 0xFFFFE000u;
            l[e] = f2tf32(wst[j][e] - __uint_as_float(h[e]));
        }
        const int sw = 4 * (((n >> 2) ^ (ks >> 2)) & 1);
        const uint32_t base = (uint32_t)((ks * 64 + n) * 8);
        *(uint4*)(smw + whi + base + (0 ^ sw)) = make_uint4(h[0], h[4], h[1], h[5]);
        *(uint4*)(smw + whi + base + (4 ^ sw)) = make_uint4(h[2], h[6], h[3], h[7]);
        *(uint4*)(smw + wlo + base + (0 ^ sw)) = make_uint4(l[0], l[4], l[1], l[5]);
        *(uint4*)(smw + wlo + base + (4 ^ sw)) = make_uint4(l[2], l[6], l[3], l[7]);
    }
}
__device__ __forceinline__ void sts_T_single(const float wst[4][8],
                                             uint32_t* __restrict__ smw,
                                             int whi, int tid)
{
    const int n = tid & 63, kh = tid >> 6;
    #pragma unroll
    for (int j = 0; j < 4; j++) {
        const int ks = kh * 4 + j;
        uint32_t h[8];
        #pragma unroll
        for (int e = 0; e < 8; e++) h[e] = f2tf32(wst[j][e]);
        const int sw = 4 * (((n >> 2) ^ (ks >> 2)) & 1);
        const uint32_t base = (uint32_t)((ks * 64 + n) * 8);
        *(uint4*)(smw + whi + base + (0 ^ sw)) = make_uint4(h[0], h[4], h[1], h[5]);
        *(uint4*)(smw + whi + base + (4 ^ sw)) = make_uint4(h[2], h[6], h[3], h[7]);
    }
}

// One 64x64x64 MMA chunk (A rows row0/row0+8; B all 64 cols).
__device__ __forceinline__ void mma_chunk(const uint32_t* __restrict__ smw,
                                          int wAhi, int wAlo, int wBhi, int wBlo,
                                          int row0, int g, int offA, bool split,
                                          float acc[8][4])
{
    #pragma unroll
    for (int ks = 0; ks < 8; ks++) {
        const int off = offA ^ (4 * ((ks >> 2) & 1));
        uint2 ah0 = *(const uint2*)(smw + wAhi + (ks * 64 + row0) * 8 + off);
        uint2 ah1 = *(const uint2*)(smw + wAhi + (ks * 64 + row0 + 8) * 8 + off);
        uint2 al0, al1;
        if (split) {
            al0 = *(const uint2*)(smw + wAlo + (ks * 64 + row0) * 8 + off);
            al1 = *(const uint2*)(smw + wAlo + (ks * 64 + row0 + 8) * 8 + off);
        }
        #pragma unroll
        for (int nt = 0; nt < 8; nt++) {
            const uint32_t ba = (uint32_t)((ks * 64 + nt * 8 + g) * 8 + off);
            uint2 bh = *(const uint2*)(smw + wBhi + ba);
            mma8(acc[nt], ah0.x, ah1.x, ah0.y, ah1.y, bh.x, bh.y);
            if (split) {
                uint2 bl = *(const uint2*)(smw + wBlo + ba);
                mma8(acc[nt], al0.x, al1.x, al0.y, al1.y, bh.x, bh.y);
                mma8(acc[nt], ah0.x, ah1.x, ah0.y, ah1.y, bl.x, bl.y);
            }
        }
    }
}

// ===========================================================================
// Merged projection GEMM (pipelined) + kfmt epilogue.
// blockIdx.z: 0=Q (split out), 1=K (split out), 2=V (single, transposed out)
// grid = (H, 128 m-tiles, 3), 128 thr.
// ===========================================================================
__global__ void __launch_bounds__(128, 2) proj_mma_kernel(const float* __restrict__ Qx,
                                                          const float* __restrict__ Kx,
                                                          const float* __restrict__ Vx,
                                                          const float* __restrict__ WQ,
                                                          const float* __restrict__ WK,
                                                          const float* __restrict__ WV)
{
    extern __shared__ uint32_t smw[];

    const int which = blockIdx.z;
    const int split = (which != 2);
    const float* __restrict__ X = (which == 0) ? Qx : (which == 1) ? Kx : Vx;
    const float* __restrict__ W = (which == 0) ? WQ : (which == 1) ? WK : WV;

    const int tid  = threadIdx.x;
    const int lane = tid & 31;
    const int w    = tid >> 5;
    const int g    = lane >> 2;
    const int t    = lane & 3;
    const int row0 = w * 16 + g;
    const int offA = 2 * t ^ (4 * ((g >> 2) & 1));
    const int pe = ((2 * t) & 3) * 2 + (t >> 1);
    const int po = ((2 * t + 1) & 3) * 2 + ((2 * t + 1) >> 2);

    const int h  = blockIdx.x;
    const int m0 = blockIdx.y * 64;
    const float* __restrict__ Wh = W + (size_t)h * (D_ * DK_);
    const float* __restrict__ Xm = X + (size_t)m0 * D_;

    float acc[8][4];
    #pragma unroll
    for (int nt = 0; nt < 8; nt++)
        #pragma unroll
        for (int j = 0; j < 4; j++) acc[nt][j] = 0.f;

    float4 xa[4], xb[4];
    float  wst[4][8];
    ldg_rows(Xm, tid, D_, xa, xb);
    ldg_T(Wh, DK_, tid, wst);

    for (int k0 = 0; k0 < D_; k0 += 64) {
        if (split) {
            sts_split(xa, xb, smw, 0, 4096, tid);
            sts_T_split(wst, smw, 8192, 12288, tid);
        } else {
            sts_single(xa, xb, smw, 0, tid);
            sts_T_single(wst, smw, 4096, tid);
        }
        if (k0 + 64 < D_) {               // stage next chunk; hidden behind MMA
            ldg_rows(Xm + k0 + 64, tid, D_, xa, xb);
            ldg_T(Wh + (size_t)(k0 + 64) * DK_, DK_, tid, wst);
        }
        __syncthreads();
        if (split) mma_chunk(smw, 0, 4096, 8192, 12288, row0, g, offA, true,  acc);
        else       mma_chunk(smw, 0, 0,    4096, 0,     row0, g, offA, false, acc);
        __syncthreads();
    }

    const int bb = m0 >> 11, st = (m0 & 2047) >> 6;
    const size_t tbase = ((size_t)(bb * H_ + h) * 32 + st) * 4096;

    if (which != 2) {
        // split epilogue: hi -> smw[0..4096), lo -> smw[4096..8192), kfmt
        #pragma unroll
        for (int j = 0; j < 2; j++) {
            const int r = row0 + 8 * j;
            #pragma unroll
            for (int nt = 0; nt < 8; nt++) {
                float p0 = acc[nt][2 * j], p1 = acc[nt][2 * j + 1];
                uint32_t h0 = __float_as_uint(p0) & 0xFFFFE000u;
                uint32_t h1 = __float_as_uint(p1) & 0xFFFFE000u;
                uint32_t l0 = f2tf32(p0 - __uint_as_float(h0));
                uint32_t l1 = f2tf32(p1 - __uint_as_float(h1));
                const int sw = 4 * ((((r >> 2) ^ (nt >> 2)) & 1));
                const uint32_t base = (uint32_t)((nt * 64 + r) * 8);
                smw[base + (pe ^ sw)] = h0;
                smw[base + (po ^ sw)] = h1;
                smw[4096 + base + (pe ^ sw)] = l0;
                smw[4096 + base + (po ^ sw)] = l1;
            }
        }
        __syncthreads();
        uint32_t* dH = (which == 0 ? g_Qhi : g_Khi) + tbase;
        uint32_t* dL = (which == 0 ? g_Qlo : g_Klo) + tbase;
        const uint4* s4 = (const uint4*)smw;
        for (int i = tid; i < 1024; i += 128) {
            ((uint4*)dH)[i] = s4[i];
            ((uint4*)dL)[i] = s4[1024 + i];
        }
    } else {
        // V epilogue: raw tf32 tile (row=s', col=dk) -> transpose -> kfmt Vt
        #pragma unroll
        for (int j = 0; j < 2; j++) {
            const int r = row0 + 8 * j;
            #pragma unroll
            for (int nt = 0; nt < 8; nt++) {
                smw[r * 64 + nt * 8 + 2 * t]     = f2tf32(acc[nt][2 * j]);
                smw[r * 64 + nt * 8 + 2 * t + 1] = f2tf32(acc[nt][2 * j + 1]);
            }
        }
        __syncthreads();
        {
            const int vdk = tid & 63, vsh = tid >> 6;
            #pragma unroll
            for (int j = 0; j < 4; j++) {
                const int sc = vsh * 4 + j;
                uint32_t v[8];
                #pragma unroll
                for (int si = 0; si < 8; si++)
                    v[si] = smw[(sc * 8 + si) * 64 + vdk];
                const int sw = 4 * (((vdk >> 2) ^ (sc >> 2)) & 1);
                const uint32_t base = (uint32_t)((sc * 64 + vdk) * 8);
                *(uint4*)(smw + 4096 + base + (0 ^ sw)) = make_uint4(v[0], v[4], v[1], v[5]);
                *(uint4*)(smw + 4096 + base + (4 ^ sw)) = make_uint4(v[2], v[6], v[3], v[7]);
            }
        }
        __syncthreads();
        uint32_t* dV = g_Vt + tbase;
        const uint4* s4 = (const uint4*)(smw + 4096);
        for (int i = tid; i < 1024; i += 128)
            ((uint4*)dV)[i] = s4[i];
    }
}

// ===========================================================================
// Output GEMM (pipelined, single tf32): out = Oc[8192,512] @ WO[512,512]
// ===========================================================================
__global__ void __launch_bounds__(128, 2) out_mma_kernel(const float* __restrict__ WO,
                                                         float* __restrict__ out)
{
    extern __shared__ uint32_t smw[];

    const int tid  = threadIdx.x;
    const int lane = tid & 31;
    const int w    = tid >> 5;
    const int g    = lane >> 2;
    const int t    = lane & 3;
    const int row0 = w * 16 + g;
    const int offA = 2 * t ^ (4 * ((g >> 2) & 1));

    const int n0 = blockIdx.x * 64;
    const int m0 = blockIdx.y * 64;
    const float* __restrict__ Am = g_Oc + (size_t)m0 * D_;

    float acc[8][4];
    #pragma unroll
    for (int nt = 0; nt < 8; nt++)
        #pragma unroll
        for (int j = 0; j < 4; j++) acc[nt][j] = 0.f;

    float4 xa[4], xb[4];
    float  wst[4][8];
    ldg_rows(Am, tid, D_, xa, xb);
    ldg_T(WO + n0, D_, tid, wst);

    for (int k0 = 0; k0 < D_; k0 += 64) {
        sts_single(xa, xb, smw, 0, tid);
        sts_T_single(wst, smw, 4096, tid);
        if (k0 + 64 < D_) {
            ldg_rows(Am + k0 + 64, tid, D_, xa, xb);
            ldg_T(WO + (size_t)(k0 + 64) * D_ + n0, D_, tid, wst);
        }
        __syncthreads();
        mma_chunk(smw, 0, 0, 4096, 0, row0, g, offA, false, acc);
        __syncthreads();
    }

    #pragma unroll
    for (int j = 0; j < 2; j++) {
        const int m = m0 + row0 + 8 * j;
        float* dst = out + (size_t)m * D_ + n0;
        #pragma unroll
        for (int nt = 0; nt < 8; nt++)
            *(float2*)(dst + nt * 8 + t * 2) = make_float2(acc[nt][2 * j], acc[nt][2 * j + 1]);
    }
}

// ===========================================================================
// Flash attention (unchanged from R9): CTA = (b, h, 128 q-rows), 256 thr.
// smem (words): buf0 [KHI 0 | KLO 4096 | VT 8192], buf1 +12288, PS 24576(x2)
// ===========================================================================
#define ABUF 12288
#define APS  24576
#define ASMEM_WORDS 32768   // 128 KB

__global__ void __launch_bounds__(256, 1) attn_mma_kernel()
{
    extern __shared__ uint32_t smw[];
    const uint32_t sbase = smem_u32(smw);

    const int tid  = threadIdx.x;
    const int lane = tid & 31;
    const int w    = tid >> 5;
    const int g    = lane >> 2;
    const int t    = lane & 3;
    const int g2   = (g >> 2) & 1;
    const int row0 = w * 16 + g;
    const int offA = 2 * t ^ (4 * g2);
    const int pe = ((2 * t) & 3) * 2 + (t >> 1);
    const int po = ((2 * t + 1) & 3) * 2 + ((2 * t + 1) >> 2);

    const int h  = blockIdx.y;
    const int b  = blockIdx.z;
    const size_t kvbase = ((size_t)(b * H_ + h)) * 32 * 4096;

    {
        const uint4* sK = (const uint4*)(g_Khi + kvbase);
        const uint4* sL = (const uint4*)(g_Klo + kvbase);
        const uint4* sV = (const uint4*)(g_Vt  + kvbase);
        #pragma unroll
        for (int k = 0; k < 4; k++) {
            const int i = tid + k * 256;
            cp16(sbase + i * 16,          sK + i);
            cp16(sbase + 16384 + i * 16,  sL + i);
            cp16(sbase + 32768 + i * 16,  sV + i);
        }
        CP_COMMIT();
    }

    uint2 qh0[8], qh1[8], ql0[8], ql1[8];
    {
        const int qst = blockIdx.x * 2 + (row0 >> 6);
        const size_t qtb = ((size_t)(b * H_ + h) * 32 + qst) * 4096;
        const int r = row0 & 63;
        #pragma unroll
        for (int ks = 0; ks < 8; ks++) {
            const int off = offA ^ (4 * ((ks >> 2) & 1));
            const size_t i0 = qtb + (ks * 64 + r) * 8 + off;
            const size_t i1 = qtb + (ks * 64 + r + 8) * 8 + off;
            qh0[ks] = *(const uint2*)(g_Qhi + i0);
            qh1[ks] = *(const uint2*)(g_Qhi + i1);
            ql0[ks] = *(const uint2*)(g_Qlo + i0);
            ql1[ks] = *(const uint2*)(g_Qlo + i1);
        }
    }

    float o[8][4];
    #pragma unroll
    for (int nt = 0; nt < 8; nt++)
        #pragma unroll
        for (int j = 0; j < 4; j++) o[nt][j] = 0.f;
    float mrun[2] = {-1e30f, -1e30f}, lrun[2] = {0.f, 0.f};
    const float Cc = 0.125f * 1.4426950408889634f;

    const int ptile = APS + (row0 >> 6) * 4096;
    const int pr    = row0 & 63;

    for (int it = 0; it < 32; it++) {
        const int cur = it & 1;

        if (it < 31) {
            const uint32_t db = sbase + (cur ^ 1) * (ABUF * 4);
            const size_t tb = kvbase + (size_t)(it + 1) * 4096;
            const uint4* sK = (const uint4*)(g_Khi + tb);
            const uint4* sL = (const uint4*)(g_Klo + tb);
            const uint4* sV = (const uint4*)(g_Vt  + tb);
            #pragma unroll
            for (int k = 0; k < 4; k++) {
                const int i = tid + k * 256;
                cp16(db + i * 16,          sK + i);
                cp16(db + 16384 + i * 16,  sL + i);
                cp16(db + 32768 + i * 16,  sV + i);
            }
            CP_COMMIT();
            asm volatile("cp.async.wait_group 1;" ::: "memory");
        } else {
            asm volatile("cp.async.wait_group 0;" ::: "memory");
        }
        __syncthreads();

        const int bk = cur * ABUF;

        float accS[8][4];
        #pragma unroll
        for (int nt = 0; nt < 8; nt++)
            #pragma unroll
            for (int j = 0; j < 4; j++) accS[nt][j] = 0.f;

        #pragma unroll
        for (int ks = 0; ks < 8; ks++) {
            const int off = offA ^ (4 * ((ks >> 2) & 1));
            #pragma unroll
            for (int nt = 0; nt < 8; nt++) {
                const uint32_t ba = (uint32_t)(bk + (ks * 64 + nt * 8 + g) * 8 + off);
                uint2 bh = *(const uint2*)(smw + ba);
                uint2 bl = *(const uint2*)(smw + 4096 + ba);
                mma8(accS[nt], qh0[ks].x, qh1[ks].x, qh0[ks].y, qh1[ks].y, bh.x, bh.y);
                mma8(accS[nt], ql0[ks].x, ql1[ks].x, ql0[ks].y, ql1[ks].y, bh.x, bh.y);
                mma8(accS[nt], qh0[ks].x, qh1[ks].x, qh0[ks].y, qh1[ks].y, bl.x, bl.y);
            }
        }

        #pragma unroll
        for (int j = 0; j < 2; j++) {
            float m = -1e30f;
            #pragma unroll
            for (int nt = 0; nt < 8; nt++)
                m = fmaxf(m, fmaxf(accS[nt][2 * j], accS[nt][2 * j + 1]));
            m = fmaxf(m, __shfl_xor_sync(0xffffffffu, m, 1));
            m = fmaxf(m, __shfl_xor_sync(0xffffffffu, m, 2));

            float mnew = fmaxf(mrun[j], m);
            float scl  = exp2f((mrun[j] - mnew) * Cc);
            mrun[j] = mnew;

            const int prow = pr + 8 * j;
            float sum = 0.f;
            #pragma unroll
            for (int nt = 0; nt < 8; nt++) {
                float p0 = exp2f((accS[nt][2 * j]     - mnew) * Cc);
                float p1 = exp2f((accS[nt][2 * j + 1] - mnew) * Cc);
                sum += p0 + p1;
                const int sw = 4 * ((g2 ^ (nt >> 2)) & 1);
                const uint32_t base = (uint32_t)(ptile + (nt * 64 + prow) * 8);
                smw[base + (pe ^ sw)] = f2tf32(p0);
                smw[base + (po ^ sw)] = f2tf32(p1);
                o[nt][2 * j]     *= scl;
                o[nt][2 * j + 1] *= scl;
            }
            sum += __shfl_xor_sync(0xffffffffu, sum, 1);
            sum += __shfl_xor_sync(0xffffffffu, sum, 2);
            lrun[j] = lrun[j] * scl + sum;
        }
        __syncwarp();

        #pragma unroll
        for (int ks = 0; ks < 8; ks++) {
            const int off = offA ^ (4 * ((ks >> 2) & 1));
            uint2 p0 = *(const uint2*)(smw + ptile + (ks * 64 + pr) * 8 + off);
            uint2 p1 = *(const uint2*)(smw + ptile + (ks * 64 + pr + 8) * 8 + off);
            #pragma unroll
            for (int nt = 0; nt < 8; nt++) {
                uint2 bv = *(const uint2*)(smw + bk + 8192 + (ks * 64 + nt * 8 + g) * 8 + off);
                mma8(o[nt], p0.x, p1.x, p0.y, p1.y, bv.x, bv.y);
            }
        }
        __syncthreads();
    }

    const int q0 = blockIdx.x * 128;
    #pragma unroll
    for (int j = 0; j < 2; j++) {
        float inv = 1.f / lrun[j];
        int r = q0 + row0 + 8 * j;
        float* dst = g_Oc + (size_t)(b * S_ + r) * D_ + h * DK_;
        #pragma unroll
        for (int nt = 0; nt < 8; nt++) {
            float2 v = make_float2(o[nt][2 * j] * inv, o[nt][2 * j + 1] * inv);
            *(float2*)(dst + nt * 8 + t * 2) = v;
        }
    }
}

// ---------------------------------------------------------------------------
extern "C" void kernel_launch(void* const* d_in, const int* in_sizes, int n_in,
                              void* d_out, int out_size)
{
    const float* Q  = (const float*)d_in[0];
    const float* K  = (const float*)d_in[1];
    const float* V  = (const float*)d_in[2];
    const float* WQ = (const float*)d_in[3];
    const float* WK = (const float*)d_in[4];
    const float* WV = (const float*)d_in[5];
    const float* WO = (const float*)d_in[6];
    float* out = (float*)d_out;

    const size_t smem64 = 65536, smem32 = 32768;
    const size_t smemA  = (size_t)ASMEM_WORDS * 4;   // 128 KB
    cudaFuncSetAttribute(proj_mma_kernel, cudaFuncAttributeMaxDynamicSharedMemorySize, (int)smem64);
    cudaFuncSetAttribute(out_mma_kernel,  cudaFuncAttributeMaxDynamicSharedMemorySize, (int)smem32);
    cudaFuncSetAttribute(attn_mma_kernel, cudaFuncAttributeMaxDynamicSharedMemorySize, (int)smemA);

    proj_mma_kernel<<<dim3(H_, (B_ * S_) / 64, 3), 128, smem64>>>(Q, K, V, WQ, WK, WV);

    attn_mma_kernel<<<dim3(S_ / 128, H_, B_), 256, smemA>>>();

    out_mma_kernel<<<dim3(D_ / 64, (B_ * S_) / 64), 128, smem32>>>(WO, out);
}